// round 7
// baseline (speedup 1.0000x reference)
#include <cuda_runtime.h>
#include <cstdint>
#include <cstddef>

#define NN 100000
#define NE 640000

typedef unsigned long long u64t;

__device__ float g_pre[(size_t)NN * 128];   // [n][0:64]=x@Wa+eb1, [64:128]=x@Wb
__device__ float g_agg[(size_t)NN * 128];   // scatter-sum of e2
__device__ float g_cnt[NN];                 // edge counts per dest node
__device__ int   g_is64;                    // edge_index dtype flag (1 = int64)

// ---------- packed f32x2 helpers ----------
__device__ __forceinline__ u64t pk2(float lo, float hi) {
    u64t r; asm("mov.b64 %0,{%1,%2};" : "=l"(r) : "f"(lo), "f"(hi)); return r;
}
__device__ __forceinline__ float2 upk(u64t v) {
    float2 r; asm("mov.b64 {%0,%1},%2;" : "=f"(r.x), "=f"(r.y) : "l"(v)); return r;
}
__device__ __forceinline__ void fma2(u64t& d, u64t a, u64t b) {
    asm("fma.rn.f32x2 %0,%1,%2,%0;" : "+l"(d) : "l"(a), "l"(b));
}

// ------------------ detect edge_index element width -------------------
__global__ void k_detect(const unsigned int* __restrict__ w) {
    unsigned int any = 0;
    for (int i = threadIdx.x; i < 1024; i += 32) any |= w[2 * i + 1];
#pragma unroll
    for (int o = 16; o > 0; o >>= 1) any |= __shfl_xor_sync(0xffffffffu, any, o);
    if (threadIdx.x == 0) g_is64 = (any == 0) ? 1 : 0;
}

// ---------------------------- zero scratch ----------------------------
__global__ void k_zero() {
    size_t i = (size_t)blockIdx.x * blockDim.x + threadIdx.x;
    size_t stride = (size_t)gridDim.x * blockDim.x;
    float4* a4 = (float4*)g_agg;
    const size_t n4 = (size_t)NN * 32;
    for (size_t j = i; j < n4; j += stride) a4[j] = make_float4(0.f, 0.f, 0.f, 0.f);
    for (size_t j = i; j < (size_t)NN; j += stride) g_cnt[j] = 0.f;
}

// ------------- kernel 1: pre[n] = x @ [Wa|Wb] (+eb1), weights via LDG -----------
__global__ void __launch_bounds__(256, 2) k_pre(
    const float* __restrict__ x, const float* __restrict__ ew1,
    const float* __restrict__ eb1) {
    extern __shared__ float sm[];
    float* sX = sm;             // 128*132 = 16896
    const int tid = threadIdx.x;
    const int n0 = blockIdx.x * 128;

#pragma unroll
    for (int it = 0; it < 16; ++it) {
        int idx = tid + it * 256;
        int r = idx >> 5, q = idx & 31;
        int n = n0 + r;
        float4 v = make_float4(0.f, 0.f, 0.f, 0.f);
        if (n < NN) v = __ldg((const float4*)(x + (size_t)n * 128) + q);
        *(float4*)(sX + r * 132 + q * 4) = v;
    }
    __syncthreads();

    const int tx = tid & 31, ty = tid >> 5;
    const int c0 = ty * 16;
    // weight base: cols c0..c0+15 of [Wa|Wb]; Wa rows at ew1, Wb rows at ew1+8192
    const ulonglong2* wp = (const ulonglong2*)(ew1 + (c0 < 64 ? c0 : 8192 + (c0 - 64)));
    u64t acc[4][8];
#pragma unroll
    for (int i = 0; i < 4; i++)
#pragma unroll
        for (int p = 0; p < 8; p++) acc[i][p] = 0ull;

    const float* er[4];
#pragma unroll
    for (int i = 0; i < 4; i++) er[i] = sX + (tx + 32 * i) * 132;

#pragma unroll 4
    for (int k0 = 0; k0 < 128; k0 += 4) {
        float4 av[4];
#pragma unroll
        for (int i = 0; i < 4; i++) av[i] = *(const float4*)(er[i] + k0);
#pragma unroll
        for (int kk = 0; kk < 4; kk++) {
            const ulonglong2* bp = wp + (size_t)(k0 + kk) * 16;
            ulonglong2 b01 = __ldg(bp), b23 = __ldg(bp + 1),
                       b45 = __ldg(bp + 2), b67 = __ldg(bp + 3);
#pragma unroll
            for (int i = 0; i < 4; i++) {
                float a = ((const float*)&av[i])[kk];
                u64t ap = pk2(a, a);
                fma2(acc[i][0], ap, b01.x); fma2(acc[i][1], ap, b01.y);
                fma2(acc[i][2], ap, b23.x); fma2(acc[i][3], ap, b23.y);
                fma2(acc[i][4], ap, b45.x); fma2(acc[i][5], ap, b45.y);
                fma2(acc[i][6], ap, b67.x); fma2(acc[i][7], ap, b67.y);
            }
        }
    }
#pragma unroll
    for (int i = 0; i < 4; i++) {
        int n = n0 + tx + 32 * i;
        if (n >= NN) continue;
        float* dst = g_pre + (size_t)n * 128 + c0;
#pragma unroll
        for (int p = 0; p < 8; p++) {
            float2 v = upk(acc[i][p]);
            int j = c0 + 2 * p;
            if (j < 64)     v.x += __ldg(eb1 + j);
            if (j + 1 < 64) v.y += __ldg(eb1 + j + 1);
            dst[2 * p] = v.x; dst[2 * p + 1] = v.y;
        }
    }
}

// ------------------- kernel 2: edges (weights via LDG, 2 CTAs/SM) ---------------
__global__ void __launch_bounds__(256, 2) k_edge(
    const float* __restrict__ ea, const void* __restrict__ ei_raw,
    const float* __restrict__ ew1, const float* __restrict__ ew2,
    const float* __restrict__ eb2, const float* __restrict__ ne_g,
    const float* __restrict__ ne_b, float* __restrict__ eout) {
    extern __shared__ float sm[];
    float* sE   = sm;                    // 128*132 = 16896
    float* sPAB = sm + 16896;            // 128*68  = 8704 (H written in place)
    int*   sRow = (int*)(sm + 25600);    // 128
    int*   sCol = sRow + 128;            // 128
    float* sEB2 = sm + 25856;            // 128  (total 25984 floats)
    const int tid = threadIdx.x;
    const int e0 = blockIdx.x * 128;
    const int is64 = g_is64;

    if (tid < 128) {
        int e = e0 + tid;
        int r, c;
        if (is64) {
            const long long* p = (const long long*)ei_raw;
            r = (int)__ldg(p + e);
            c = (int)__ldg(p + (size_t)NE + e);
        } else {
            const int* p = (const int*)ei_raw;
            r = __ldg(p + e);
            c = __ldg(p + (size_t)NE + e);
        }
        sRow[tid] = min(max(r, 0), NN - 1);
        sCol[tid] = min(max(c, 0), NN - 1);
        sEB2[tid] = __ldg(eb2 + tid);
    }
    // gather pa[row]+pb[col] — indices read directly from gmem so these L2-latency
    // loads overlap the sE fill below (no intervening barrier).
#pragma unroll
    for (int it = 0; it < 8; ++it) {
        int idx = tid + it * 256;
        int el = idx >> 4, q = idx & 15;
        int e = e0 + el;
        int rn, cn;
        if (is64) {
            const long long* p = (const long long*)ei_raw;
            rn = (int)__ldg(p + e);
            cn = (int)__ldg(p + (size_t)NE + e);
        } else {
            const int* p = (const int*)ei_raw;
            rn = __ldg(p + e);
            cn = __ldg(p + (size_t)NE + e);
        }
        rn = min(max(rn, 0), NN - 1);
        cn = min(max(cn, 0), NN - 1);
        float4 va = __ldg((const float4*)(g_pre + (size_t)rn * 128) + q);
        float4 vb = __ldg((const float4*)(g_pre + (size_t)cn * 128) + 16 + q);
        float* dst = sPAB + el * 68 + q * 4;
        dst[0] = va.x + vb.x; dst[1] = va.y + vb.y;
        dst[2] = va.z + vb.z; dst[3] = va.w + vb.w;
    }
#pragma unroll
    for (int it = 0; it < 16; ++it) {
        int idx = tid + it * 256;
        int r = idx >> 5, q = idx & 31;
        float4 v = __ldg((const float4*)(ea + (size_t)(e0 + r) * 128) + q);
        *(float4*)(sE + r * 132 + q * 4) = v;
    }
    __syncthreads();

    const int tx = tid & 31, ty = tid >> 5;
    // stage 1: H[128][64] = relu(E@We + PAB), H overwrites PAB in place
    {
        const int c0 = ty * 8;
        const ulonglong2* wp = (const ulonglong2*)(ew1 + 16384 + c0);  // We rows
        u64t acc[4][4];
#pragma unroll
        for (int i = 0; i < 4; i++)
#pragma unroll
            for (int p = 0; p < 4; p++) acc[i][p] = 0ull;
        const float* er[4];
#pragma unroll
        for (int i = 0; i < 4; i++) er[i] = sE + (tx + 32 * i) * 132;
#pragma unroll 8
        for (int k0 = 0; k0 < 128; k0 += 4) {
            float4 av[4];
#pragma unroll
            for (int i = 0; i < 4; i++) av[i] = *(const float4*)(er[i] + k0);
#pragma unroll
            for (int kk = 0; kk < 4; kk++) {
                const ulonglong2* bp = wp + (size_t)(k0 + kk) * 16;
                ulonglong2 b01 = __ldg(bp), b23 = __ldg(bp + 1);
#pragma unroll
                for (int i = 0; i < 4; i++) {
                    float a = ((const float*)&av[i])[kk];
                    u64t ap = pk2(a, a);
                    fma2(acc[i][0], ap, b01.x); fma2(acc[i][1], ap, b01.y);
                    fma2(acc[i][2], ap, b23.x); fma2(acc[i][3], ap, b23.y);
                }
            }
        }
#pragma unroll
        for (int i = 0; i < 4; i++) {
            int r = tx + 32 * i;
            float* hd = sPAB + r * 68 + c0;    // read pab, write H same cells
#pragma unroll
            for (int p = 0; p < 4; p++) {
                float2 v = upk(acc[i][p]);
                float p0 = hd[2 * p], p1 = hd[2 * p + 1];
                hd[2 * p]     = fmaxf(v.x + p0, 0.f);
                hd[2 * p + 1] = fmaxf(v.y + p1, 0.f);
            }
        }
    }
    __syncthreads();
    // stage 2: e2 = H@ew2 + eb2 + e  (written back into sE, same-thread cells)
    {
        const int c1 = ty * 16;
        const ulonglong2* wp = (const ulonglong2*)(ew2 + c1);
        u64t acc[4][8];
#pragma unroll
        for (int i = 0; i < 4; i++)
#pragma unroll
            for (int p = 0; p < 8; p++) acc[i][p] = 0ull;
        const float* hr[4];
#pragma unroll
        for (int i = 0; i < 4; i++) hr[i] = sPAB + (tx + 32 * i) * 68;
#pragma unroll 4
        for (int k0 = 0; k0 < 64; k0 += 4) {
            float4 av[4];
#pragma unroll
            for (int i = 0; i < 4; i++) av[i] = *(const float4*)(hr[i] + k0);
#pragma unroll
            for (int kk = 0; kk < 4; kk++) {
                const ulonglong2* bp = wp + (size_t)(k0 + kk) * 32;
                ulonglong2 b01 = __ldg(bp),     b23 = __ldg(bp + 1),
                           b45 = __ldg(bp + 2), b67 = __ldg(bp + 3);
#pragma unroll
                for (int i = 0; i < 4; i++) {
                    float a = ((const float*)&av[i])[kk];
                    u64t ap = pk2(a, a);
                    fma2(acc[i][0], ap, b01.x); fma2(acc[i][1], ap, b01.y);
                    fma2(acc[i][2], ap, b23.x); fma2(acc[i][3], ap, b23.y);
                    fma2(acc[i][4], ap, b45.x); fma2(acc[i][5], ap, b45.y);
                    fma2(acc[i][6], ap, b67.x); fma2(acc[i][7], ap, b67.y);
                }
            }
        }
#pragma unroll
        for (int i = 0; i < 4; i++) {
            int r = tx + 32 * i;
            float* erow = sE + r * 132 + c1;
#pragma unroll
            for (int p = 0; p < 8; p++) {
                float2 v = upk(acc[i][p]);
                int j = c1 + 2 * p;
                erow[2 * p]     += v.x + sEB2[j];
                erow[2 * p + 1] += v.y + sEB2[j + 1];
            }
        }
    }
    __syncthreads();
    // LayerNorm + vector-atomic scatter (2 threads per edge row)
    {
        const int r = tid >> 1, half = tid & 1;
        const float* rowp = sE + r * 132 + half * 64;
        float s = 0.f, s2 = 0.f;
#pragma unroll 8
        for (int k = 0; k < 64; k++) { float t = rowp[k]; s += t; s2 = fmaf(t, t, s2); }
        s  += __shfl_xor_sync(0xffffffffu, s, 1);
        s2 += __shfl_xor_sync(0xffffffffu, s2, 1);
        const float mu  = s * 0.0078125f;
        const float var = fmaf(-mu, mu, s2 * 0.0078125f);
        const float rstd = rsqrtf(var + 1e-5f);
        const int e = e0 + r;
        float* outp = eout + (size_t)e * 128 + half * 64;
        const int cn = sCol[r];
        float4* aggp = (float4*)(g_agg + (size_t)cn * 128 + half * 64);
#pragma unroll
        for (int q = 0; q < 16; q++) {
            float v0 = rowp[4 * q], v1 = rowp[4 * q + 1];
            float v2 = rowp[4 * q + 2], v3 = rowp[4 * q + 3];
            atomicAdd(aggp + q, make_float4(v0, v1, v2, v3));
            int j = half * 64 + 4 * q;
            float4 o;
            o.x = fmaf((v0 - mu) * rstd, __ldg(ne_g + j),     __ldg(ne_b + j));
            o.y = fmaf((v1 - mu) * rstd, __ldg(ne_g + j + 1), __ldg(ne_b + j + 1));
            o.z = fmaf((v2 - mu) * rstd, __ldg(ne_g + j + 2), __ldg(ne_b + j + 2));
            o.w = fmaf((v3 - mu) * rstd, __ldg(ne_g + j + 3), __ldg(ne_b + j + 3));
            *(float4*)(outp + 4 * q) = o;
        }
        if (half == 0) atomicAdd(g_cnt + cn, 1.0f);
    }
}

// ------------------- kernel 3: nodes (64/block, weights via LDG) ----------------
__global__ void __launch_bounds__(256, 2) k_node(
    const float* __restrict__ x, const float* __restrict__ nw1,
    const float* __restrict__ nb1, const float* __restrict__ nw2,
    const float* __restrict__ nb2, const float* __restrict__ nx_g,
    const float* __restrict__ nx_b, float* __restrict__ xout) {
    extern __shared__ float sm[];
    float* sX = sm;              // 64*132 = 8448
    float* sA = sm + 8448;       // 64*132 = 8448
    float* sH = sm + 16896;      // 64*68  = 4352  (total 21248 floats)
    const int tid = threadIdx.x;
    const int n0 = blockIdx.x * 64;

#pragma unroll
    for (int it = 0; it < 8; ++it) {
        int idx = tid + it * 256;
        int r = idx >> 5, q = idx & 31;
        int n = n0 + r;
        float4 v = make_float4(0.f, 0.f, 0.f, 0.f);
        float4 w4 = make_float4(0.f, 0.f, 0.f, 0.f);
        if (n < NN) {
            v = __ldg((const float4*)(x + (size_t)n * 128) + q);
            float c = g_cnt[n];
            float inv = 1.0f / fmaxf(c, 1.0f);
            float4 a = *((const float4*)(g_agg + (size_t)n * 128) + q);
            w4 = make_float4(a.x * inv, a.y * inv, a.z * inv, a.w * inv);
        }
        *(float4*)(sX + r * 132 + q * 4) = v;
        *(float4*)(sA + r * 132 + q * 4) = w4;
    }
    __syncthreads();

    const int tx = tid & 31, ty = tid >> 5;
    const int c0 = ty * 8;
    const ulonglong2* w1p = (const ulonglong2*)(nw1 + c0);
    u64t acc[2][4];
#pragma unroll
    for (int i = 0; i < 2; i++)
#pragma unroll
        for (int p = 0; p < 4; p++) acc[i][p] = 0ull;
    // pass A: x @ nw1[0:128]
    {
        const float* er[2];
#pragma unroll
        for (int i = 0; i < 2; i++) er[i] = sX + (tx + 32 * i) * 132;
#pragma unroll 8
        for (int k0 = 0; k0 < 128; k0 += 4) {
            float4 av[2];
#pragma unroll
            for (int i = 0; i < 2; i++) av[i] = *(const float4*)(er[i] + k0);
#pragma unroll
            for (int kk = 0; kk < 4; kk++) {
                const ulonglong2* bp = w1p + (size_t)(k0 + kk) * 16;
                ulonglong2 b01 = __ldg(bp), b23 = __ldg(bp + 1);
#pragma unroll
                for (int i = 0; i < 2; i++) {
                    float a = ((const float*)&av[i])[kk];
                    u64t ap = pk2(a, a);
                    fma2(acc[i][0], ap, b01.x); fma2(acc[i][1], ap, b01.y);
                    fma2(acc[i][2], ap, b23.x); fma2(acc[i][3], ap, b23.y);
                }
            }
        }
    }
    // pass B: agg @ nw1[128:256]
    {
        const float* er[2];
#pragma unroll
        for (int i = 0; i < 2; i++) er[i] = sA + (tx + 32 * i) * 132;
#pragma unroll 8
        for (int k0 = 0; k0 < 128; k0 += 4) {
            float4 av[2];
#pragma unroll
            for (int i = 0; i < 2; i++) av[i] = *(const float4*)(er[i] + k0);
#pragma unroll
            for (int kk = 0; kk < 4; kk++) {
                const ulonglong2* bp = w1p + (size_t)(128 + k0 + kk) * 16;
                ulonglong2 b01 = __ldg(bp), b23 = __ldg(bp + 1);
#pragma unroll
                for (int i = 0; i < 2; i++) {
                    float a = ((const float*)&av[i])[kk];
                    u64t ap = pk2(a, a);
                    fma2(acc[i][0], ap, b01.x); fma2(acc[i][1], ap, b01.y);
                    fma2(acc[i][2], ap, b23.x); fma2(acc[i][3], ap, b23.y);
                }
            }
        }
    }
#pragma unroll
    for (int i = 0; i < 2; i++) {
        int r = tx + 32 * i;
        float* hd = sH + r * 68 + c0;
#pragma unroll
        for (int p = 0; p < 4; p++) {
            float2 v = upk(acc[i][p]);
            hd[2 * p]     = fmaxf(v.x + __ldg(nb1 + c0 + 2 * p), 0.f);
            hd[2 * p + 1] = fmaxf(v.y + __ldg(nb1 + c0 + 2 * p + 1), 0.f);
        }
    }
    __syncthreads();
    // stage 2: x2 = x + H@nw2 + nb2 (into sX)
    {
        const int c1 = ty * 16;
        const ulonglong2* w2p = (const ulonglong2*)(nw2 + c1);
        u64t acc2[2][8];
#pragma unroll
        for (int i = 0; i < 2; i++)
#pragma unroll
            for (int p = 0; p < 8; p++) acc2[i][p] = 0ull;
        const float* hr[2];
#pragma unroll
        for (int i = 0; i < 2; i++) hr[i] = sH + (tx + 32 * i) * 68;
#pragma unroll 4
        for (int k0 = 0; k0 < 64; k0 += 4) {
            float4 av[2];
#pragma unroll
            for (int i = 0; i < 2; i++) av[i] = *(const float4*)(hr[i] + k0);
#pragma unroll
            for (int kk = 0; kk < 4; kk++) {
                const ulonglong2* bp = w2p + (size_t)(k0 + kk) * 32;
                ulonglong2 b01 = __ldg(bp),     b23 = __ldg(bp + 1),
                           b45 = __ldg(bp + 2), b67 = __ldg(bp + 3);
#pragma unroll
                for (int i = 0; i < 2; i++) {
                    float a = ((const float*)&av[i])[kk];
                    u64t ap = pk2(a, a);
                    fma2(acc2[i][0], ap, b01.x); fma2(acc2[i][1], ap, b01.y);
                    fma2(acc2[i][2], ap, b23.x); fma2(acc2[i][3], ap, b23.y);
                    fma2(acc2[i][4], ap, b45.x); fma2(acc2[i][5], ap, b45.y);
                    fma2(acc2[i][6], ap, b67.x); fma2(acc2[i][7], ap, b67.y);
                }
            }
        }
#pragma unroll
        for (int i = 0; i < 2; i++) {
            int r = tx + 32 * i;
            float* xrow = sX + r * 132 + c1;
#pragma unroll
            for (int p = 0; p < 8; p++) {
                float2 v = upk(acc2[i][p]);
                int j = c1 + 2 * p;
                xrow[2 * p]     += v.x + __ldg(nb2 + j);
                xrow[2 * p + 1] += v.y + __ldg(nb2 + j + 1);
            }
        }
    }
    __syncthreads();
    // LayerNorm -> x_out (4 threads per row, 64 rows)
    {
        const int r = tid >> 2, qtr = tid & 3;
        const float* rowp = sX + r * 132 + qtr * 32;
        float s = 0.f, s2 = 0.f;
#pragma unroll 8
        for (int k = 0; k < 32; k++) { float t = rowp[k]; s += t; s2 = fmaf(t, t, s2); }
        s  += __shfl_xor_sync(0xffffffffu, s, 1);
        s2 += __shfl_xor_sync(0xffffffffu, s2, 1);
        s  += __shfl_xor_sync(0xffffffffu, s, 2);
        s2 += __shfl_xor_sync(0xffffffffu, s2, 2);
        const float mu  = s * 0.0078125f;
        const float var = fmaf(-mu, mu, s2 * 0.0078125f);
        const float rstd = rsqrtf(var + 1e-5f);
        const int n = n0 + r;
        if (n < NN) {
            float* outp = xout + (size_t)n * 128 + qtr * 32;
#pragma unroll
            for (int q = 0; q < 8; q++) {
                float v0 = rowp[4 * q], v1 = rowp[4 * q + 1];
                float v2 = rowp[4 * q + 2], v3 = rowp[4 * q + 3];
                int j = qtr * 32 + 4 * q;
                float4 o;
                o.x = fmaf((v0 - mu) * rstd, __ldg(nx_g + j),     __ldg(nx_b + j));
                o.y = fmaf((v1 - mu) * rstd, __ldg(nx_g + j + 1), __ldg(nx_b + j + 1));
                o.z = fmaf((v2 - mu) * rstd, __ldg(nx_g + j + 2), __ldg(nx_b + j + 2));
                o.w = fmaf((v3 - mu) * rstd, __ldg(nx_g + j + 3), __ldg(nx_b + j + 3));
                *(float4*)(outp + 4 * q) = o;
            }
        }
    }
}

// --------------------------------- launch ---------------------------------------
extern "C" void kernel_launch(void* const* d_in, const int* in_sizes, int n_in,
                              void* d_out, int out_size) {
    const float* x   = (const float*)d_in[0];
    const void*  ei  = d_in[1];               // int32 or int64 — detected on device
    const float* ea  = (const float*)d_in[2];
    const float* ew1 = (const float*)d_in[4];
    const float* eb1 = (const float*)d_in[5];
    const float* ew2 = (const float*)d_in[6];
    const float* eb2 = (const float*)d_in[7];
    const float* nw1 = (const float*)d_in[8];
    const float* nb1 = (const float*)d_in[9];
    const float* nw2 = (const float*)d_in[10];
    const float* nb2 = (const float*)d_in[11];
    const float* nxg = (const float*)d_in[12];
    const float* nxb = (const float*)d_in[13];
    const float* neg_ = (const float*)d_in[14];
    const float* neb_ = (const float*)d_in[15];
    float* xout = (float*)d_out;
    float* eout = xout + (size_t)NN * 128;

    const int SM_PRE  = 16896 * 4;   // 67584
    const int SM_EDGE = 25984 * 4;   // 103936
    const int SM_NODE = 21248 * 4;   // 84992
    cudaFuncSetAttribute(k_pre,  cudaFuncAttributeMaxDynamicSharedMemorySize, SM_PRE);
    cudaFuncSetAttribute(k_edge, cudaFuncAttributeMaxDynamicSharedMemorySize, SM_EDGE);
    cudaFuncSetAttribute(k_node, cudaFuncAttributeMaxDynamicSharedMemorySize, SM_NODE);

    k_detect<<<1, 32>>>((const unsigned int*)ei);
    k_zero<<<1024, 256>>>();
    k_pre <<<(NN + 127) / 128, 256, SM_PRE>>>(x, ew1, eb1);
    k_edge<<<NE / 128, 256, SM_EDGE>>>(ea, ei, ew1, ew2, eb2, neg_, neb_, eout);
    k_node<<<(NN + 63) / 64, 256, SM_NODE>>>(x, nw1, nb1, nw2, nb2, nxg, nxb, xout);
}

// round 8
// speedup vs baseline: 1.0353x; 1.0353x over previous
#include <cuda_runtime.h>
#include <cstdint>
#include <cstddef>

#define NN 100000
#define NE 640000

typedef unsigned long long u64t;

__device__ float g_pre[(size_t)NN * 128];   // [n][0:64]=x@Wa+eb1, [64:128]=x@Wb
__device__ float g_agg[(size_t)NN * 128];   // scatter-sum of e2
__device__ float g_cnt[NN];                 // edge counts per dest node
__device__ int   g_is64;                    // edge_index dtype flag (1 = int64)

// ---------- packed f32x2 helpers ----------
__device__ __forceinline__ u64t pk2(float lo, float hi) {
    u64t r; asm("mov.b64 %0,{%1,%2};" : "=l"(r) : "f"(lo), "f"(hi)); return r;
}
__device__ __forceinline__ float2 upk(u64t v) {
    float2 r; asm("mov.b64 {%0,%1},%2;" : "=f"(r.x), "=f"(r.y) : "l"(v)); return r;
}
__device__ __forceinline__ void fma2(u64t& d, u64t a, u64t b) {
    asm("fma.rn.f32x2 %0,%1,%2,%0;" : "+l"(d) : "l"(a), "l"(b));
}

// ------------------ detect edge_index element width -------------------
__global__ void k_detect(const unsigned int* __restrict__ w) {
    unsigned int any = 0;
    for (int i = threadIdx.x; i < 1024; i += 32) any |= w[2 * i + 1];
#pragma unroll
    for (int o = 16; o > 0; o >>= 1) any |= __shfl_xor_sync(0xffffffffu, any, o);
    if (threadIdx.x == 0) g_is64 = (any == 0) ? 1 : 0;
}

// ---------------------------- zero scratch ----------------------------
__global__ void k_zero() {
    size_t i = (size_t)blockIdx.x * blockDim.x + threadIdx.x;
    size_t stride = (size_t)gridDim.x * blockDim.x;
    float4* a4 = (float4*)g_agg;
    const size_t n4 = (size_t)NN * 32;
    for (size_t j = i; j < n4; j += stride) a4[j] = make_float4(0.f, 0.f, 0.f, 0.f);
    for (size_t j = i; j < (size_t)NN; j += stride) g_cnt[j] = 0.f;
}

// ------------- kernel 1: pre[n] = x @ [Wa|Wb] (+eb1), 2D warp tiling ------------
// warp grid 4 row-panels x 2 col-panels; warp tile 32 rows x 64 cols;
// thread: rg=lane>>2 (8 row groups), cg=lane&3 (4 col groups) -> 4 rows x 16 cols.
__global__ void __launch_bounds__(256, 2) k_pre(
    const float* __restrict__ x, const float* __restrict__ ew1,
    const float* __restrict__ eb1) {
    extern __shared__ float sm[];
    float* sX = sm;             // 128*132 = 16896
    const int tid = threadIdx.x;
    const int n0 = blockIdx.x * 128;

#pragma unroll
    for (int it = 0; it < 16; ++it) {
        int idx = tid + it * 256;
        int r = idx >> 5, q = idx & 31;
        int n = n0 + r;
        float4 v = make_float4(0.f, 0.f, 0.f, 0.f);
        if (n < NN) v = __ldg((const float4*)(x + (size_t)n * 128) + q);
        *(float4*)(sX + r * 132 + q * 4) = v;
    }
    __syncthreads();

    const int lane = tid & 31, w = tid >> 5;
    const int wr = w >> 1, wc = w & 1;
    const int rg = lane >> 2, cg = lane & 3;
    // cols wc*64 + cg*16 .. +15 of [Wa|Wb]
    const float* wbase = (wc ? ew1 + 8192 : ew1) + cg * 16;
    const ulonglong2* wp = (const ulonglong2*)wbase;
    u64t acc[4][8];
#pragma unroll
    for (int i = 0; i < 4; i++)
#pragma unroll
        for (int p = 0; p < 8; p++) acc[i][p] = 0ull;

    const float* er[4];
#pragma unroll
    for (int i = 0; i < 4; i++) er[i] = sX + (wr * 32 + rg + 8 * i) * 132;

#pragma unroll 4
    for (int k0 = 0; k0 < 128; k0 += 4) {
        float4 av[4];
#pragma unroll
        for (int i = 0; i < 4; i++) av[i] = *(const float4*)(er[i] + k0);
#pragma unroll
        for (int kk = 0; kk < 4; kk++) {
            const ulonglong2* bp = wp + (size_t)(k0 + kk) * 16;  // k*64 floats
            ulonglong2 b01 = __ldg(bp),     b23 = __ldg(bp + 1),
                       b45 = __ldg(bp + 2), b67 = __ldg(bp + 3);
#pragma unroll
            for (int i = 0; i < 4; i++) {
                float a = ((const float*)&av[i])[kk];
                u64t ap = pk2(a, a);
                fma2(acc[i][0], ap, b01.x); fma2(acc[i][1], ap, b01.y);
                fma2(acc[i][2], ap, b23.x); fma2(acc[i][3], ap, b23.y);
                fma2(acc[i][4], ap, b45.x); fma2(acc[i][5], ap, b45.y);
                fma2(acc[i][6], ap, b67.x); fma2(acc[i][7], ap, b67.y);
            }
        }
    }
    const int ccol = wc * 64 + cg * 16;
#pragma unroll
    for (int i = 0; i < 4; i++) {
        int n = n0 + wr * 32 + rg + 8 * i;
        if (n >= NN) continue;
        float* dst = g_pre + (size_t)n * 128 + ccol;
#pragma unroll
        for (int p = 0; p < 8; p++) {
            float2 v = upk(acc[i][p]);
            if (wc == 0) {                       // Wa half gets eb1
                int j = cg * 16 + 2 * p;
                v.x += __ldg(eb1 + j);
                v.y += __ldg(eb1 + j + 1);
            }
            dst[2 * p] = v.x; dst[2 * p + 1] = v.y;
        }
    }
}

// ------------------- kernel 2: edges (2D warp tiling, coalesced LN) -------------
__global__ void __launch_bounds__(256, 2) k_edge(
    const float* __restrict__ ea, const void* __restrict__ ei_raw,
    const float* __restrict__ ew1, const float* __restrict__ ew2,
    const float* __restrict__ eb2, const float* __restrict__ ne_g,
    const float* __restrict__ ne_b, float* __restrict__ eout) {
    extern __shared__ float sm[];
    float* sE   = sm;                    // 128*132 = 16896
    float* sPAB = sm + 16896;            // 128*68  = 8704 (H written in place)
    int*   sRow = (int*)(sm + 25600);    // 128
    int*   sCol = sRow + 128;            // 128
    float* sEB2 = sm + 25856;            // 128  (total 25984 floats)
    const int tid = threadIdx.x;
    const int e0 = blockIdx.x * 128;
    const int is64 = g_is64;

    if (tid < 128) {
        int e = e0 + tid;
        int r, c;
        if (is64) {
            const long long* p = (const long long*)ei_raw;
            r = (int)__ldg(p + e);
            c = (int)__ldg(p + (size_t)NE + e);
        } else {
            const int* p = (const int*)ei_raw;
            r = __ldg(p + e);
            c = __ldg(p + (size_t)NE + e);
        }
        sRow[tid] = min(max(r, 0), NN - 1);
        sCol[tid] = min(max(c, 0), NN - 1);
        sEB2[tid] = __ldg(eb2 + tid);
    }
    // gather pa[row]+pb[col]
#pragma unroll
    for (int it = 0; it < 8; ++it) {
        int idx = tid + it * 256;
        int el = idx >> 4, q = idx & 15;
        int e = e0 + el;
        int rn, cn;
        if (is64) {
            const long long* p = (const long long*)ei_raw;
            rn = (int)__ldg(p + e);
            cn = (int)__ldg(p + (size_t)NE + e);
        } else {
            const int* p = (const int*)ei_raw;
            rn = __ldg(p + e);
            cn = __ldg(p + (size_t)NE + e);
        }
        rn = min(max(rn, 0), NN - 1);
        cn = min(max(cn, 0), NN - 1);
        float4 va = __ldg((const float4*)(g_pre + (size_t)rn * 128) + q);
        float4 vb = __ldg((const float4*)(g_pre + (size_t)cn * 128) + 16 + q);
        float* dst = sPAB + el * 68 + q * 4;
        dst[0] = va.x + vb.x; dst[1] = va.y + vb.y;
        dst[2] = va.z + vb.z; dst[3] = va.w + vb.w;
    }
#pragma unroll
    for (int it = 0; it < 16; ++it) {
        int idx = tid + it * 256;
        int r = idx >> 5, q = idx & 31;
        float4 v = __ldg((const float4*)(ea + (size_t)(e0 + r) * 128) + q);
        *(float4*)(sE + r * 132 + q * 4) = v;
    }
    __syncthreads();

    const int lane = tid & 31, w = tid >> 5;
    const int wr = w >> 1, wc = w & 1;
    const int rg = lane >> 2, cg = lane & 3;
    // stage 1: H = relu(E@We + PAB); warp tile 32x32, thread 4 rows x 8 cols
    {
        const int c0 = wc * 32 + cg * 8;
        const ulonglong2* wp = (const ulonglong2*)(ew1 + 16384 + c0);
        u64t acc[4][4];
#pragma unroll
        for (int i = 0; i < 4; i++)
#pragma unroll
            for (int p = 0; p < 4; p++) acc[i][p] = 0ull;
        const float* er[4];
#pragma unroll
        for (int i = 0; i < 4; i++) er[i] = sE + (wr * 32 + rg + 8 * i) * 132;
#pragma unroll 8
        for (int k0 = 0; k0 < 128; k0 += 4) {
            float4 av[4];
#pragma unroll
            for (int i = 0; i < 4; i++) av[i] = *(const float4*)(er[i] + k0);
#pragma unroll
            for (int kk = 0; kk < 4; kk++) {
                const ulonglong2* bp = wp + (size_t)(k0 + kk) * 16;
                ulonglong2 b01 = __ldg(bp), b23 = __ldg(bp + 1);
#pragma unroll
                for (int i = 0; i < 4; i++) {
                    float a = ((const float*)&av[i])[kk];
                    u64t ap = pk2(a, a);
                    fma2(acc[i][0], ap, b01.x); fma2(acc[i][1], ap, b01.y);
                    fma2(acc[i][2], ap, b23.x); fma2(acc[i][3], ap, b23.y);
                }
            }
        }
#pragma unroll
        for (int i = 0; i < 4; i++) {
            int r = wr * 32 + rg + 8 * i;
            float* hd = sPAB + r * 68 + c0;    // read pab, write H same cells
#pragma unroll
            for (int p = 0; p < 4; p++) {
                float2 v = upk(acc[i][p]);
                float p0 = hd[2 * p], p1 = hd[2 * p + 1];
                hd[2 * p]     = fmaxf(v.x + p0, 0.f);
                hd[2 * p + 1] = fmaxf(v.y + p1, 0.f);
            }
        }
    }
    __syncthreads();
    // stage 2: e2 = H@ew2 + eb2 + e; warp tile 32x64, thread 4 rows x 16 cols
    {
        const int c1 = wc * 64 + cg * 16;
        const ulonglong2* wp = (const ulonglong2*)(ew2 + c1);
        u64t acc[4][8];
#pragma unroll
        for (int i = 0; i < 4; i++)
#pragma unroll
            for (int p = 0; p < 8; p++) acc[i][p] = 0ull;
        const float* hr[4];
#pragma unroll
        for (int i = 0; i < 4; i++) hr[i] = sPAB + (wr * 32 + rg + 8 * i) * 68;
#pragma unroll 4
        for (int k0 = 0; k0 < 64; k0 += 4) {
            float4 av[4];
#pragma unroll
            for (int i = 0; i < 4; i++) av[i] = *(const float4*)(hr[i] + k0);
#pragma unroll
            for (int kk = 0; kk < 4; kk++) {
                const ulonglong2* bp = wp + (size_t)(k0 + kk) * 32;
                ulonglong2 b01 = __ldg(bp),     b23 = __ldg(bp + 1),
                           b45 = __ldg(bp + 2), b67 = __ldg(bp + 3);
#pragma unroll
                for (int i = 0; i < 4; i++) {
                    float a = ((const float*)&av[i])[kk];
                    u64t ap = pk2(a, a);
                    fma2(acc[i][0], ap, b01.x); fma2(acc[i][1], ap, b01.y);
                    fma2(acc[i][2], ap, b23.x); fma2(acc[i][3], ap, b23.y);
                    fma2(acc[i][4], ap, b45.x); fma2(acc[i][5], ap, b45.y);
                    fma2(acc[i][6], ap, b67.x); fma2(acc[i][7], ap, b67.y);
                }
            }
        }
#pragma unroll
        for (int i = 0; i < 4; i++) {
            int r = wr * 32 + rg + 8 * i;
            float* erow = sE + r * 132 + c1;
#pragma unroll
            for (int p = 0; p < 8; p++) {
                float2 v = upk(acc[i][p]);
                int j = c1 + 2 * p;
                erow[2 * p]     += v.x + sEB2[j];
                erow[2 * p + 1] += v.y + sEB2[j + 1];
            }
        }
    }
    __syncthreads();
    // LayerNorm + scatter: 8 threads/edge, float4 index q*8+oct -> each RED/STG
    // instruction covers 4 edges x 8 lanes x 16B contiguous (4 lines/instr).
    {
        const int oct = tid & 7;
#pragma unroll
        for (int ov = 0; ov < 4; ov++) {
            const int r = ov * 32 + (tid >> 3);
            const float* rowb = sE + r * 132;
            float4 vals[4];
            float s = 0.f, s2 = 0.f;
#pragma unroll
            for (int q = 0; q < 4; q++) {
                vals[q] = *(const float4*)(rowb + (q * 8 + oct) * 4);
                s += vals[q].x + vals[q].y + vals[q].z + vals[q].w;
                s2 = fmaf(vals[q].x, vals[q].x, s2);
                s2 = fmaf(vals[q].y, vals[q].y, s2);
                s2 = fmaf(vals[q].z, vals[q].z, s2);
                s2 = fmaf(vals[q].w, vals[q].w, s2);
            }
            s  += __shfl_xor_sync(0xffffffffu, s, 1);
            s2 += __shfl_xor_sync(0xffffffffu, s2, 1);
            s  += __shfl_xor_sync(0xffffffffu, s, 2);
            s2 += __shfl_xor_sync(0xffffffffu, s2, 2);
            s  += __shfl_xor_sync(0xffffffffu, s, 4);
            s2 += __shfl_xor_sync(0xffffffffu, s2, 4);
            const float mu  = s * 0.0078125f;
            const float var = fmaf(-mu, mu, s2 * 0.0078125f);
            const float rstd = rsqrtf(var + 1e-5f);
            const int e = e0 + r;
            const int cn = sCol[r];
            float* outb = eout + (size_t)e * 128;
            float4* aggb = (float4*)(g_agg + (size_t)cn * 128);
#pragma unroll
            for (int q = 0; q < 4; q++) {
                int f4 = q * 8 + oct;
                atomicAdd(aggb + f4, vals[q]);
                int j = f4 * 4;
                float4 o;
                o.x = fmaf((vals[q].x - mu) * rstd, __ldg(ne_g + j),     __ldg(ne_b + j));
                o.y = fmaf((vals[q].y - mu) * rstd, __ldg(ne_g + j + 1), __ldg(ne_b + j + 1));
                o.z = fmaf((vals[q].z - mu) * rstd, __ldg(ne_g + j + 2), __ldg(ne_b + j + 2));
                o.w = fmaf((vals[q].w - mu) * rstd, __ldg(ne_g + j + 3), __ldg(ne_b + j + 3));
                *(float4*)(outb + j) = o;
            }
            if (oct == 0) atomicAdd(g_cnt + cn, 1.0f);
        }
    }
}

// ------------------- kernel 3: nodes (64/block, weights via LDG) — R7 -----------
__global__ void __launch_bounds__(256, 2) k_node(
    const float* __restrict__ x, const float* __restrict__ nw1,
    const float* __restrict__ nb1, const float* __restrict__ nw2,
    const float* __restrict__ nb2, const float* __restrict__ nx_g,
    const float* __restrict__ nx_b, float* __restrict__ xout) {
    extern __shared__ float sm[];
    float* sX = sm;              // 64*132 = 8448
    float* sA = sm + 8448;       // 64*132 = 8448
    float* sH = sm + 16896;      // 64*68  = 4352  (total 21248 floats)
    const int tid = threadIdx.x;
    const int n0 = blockIdx.x * 64;

#pragma unroll
    for (int it = 0; it < 8; ++it) {
        int idx = tid + it * 256;
        int r = idx >> 5, q = idx & 31;
        int n = n0 + r;
        float4 v = make_float4(0.f, 0.f, 0.f, 0.f);
        float4 w4 = make_float4(0.f, 0.f, 0.f, 0.f);
        if (n < NN) {
            v = __ldg((const float4*)(x + (size_t)n * 128) + q);
            float c = g_cnt[n];
            float inv = 1.0f / fmaxf(c, 1.0f);
            float4 a = *((const float4*)(g_agg + (size_t)n * 128) + q);
            w4 = make_float4(a.x * inv, a.y * inv, a.z * inv, a.w * inv);
        }
        *(float4*)(sX + r * 132 + q * 4) = v;
        *(float4*)(sA + r * 132 + q * 4) = w4;
    }
    __syncthreads();

    const int tx = tid & 31, ty = tid >> 5;
    const int c0 = ty * 8;
    const ulonglong2* w1p = (const ulonglong2*)(nw1 + c0);
    u64t acc[2][4];
#pragma unroll
    for (int i = 0; i < 2; i++)
#pragma unroll
        for (int p = 0; p < 4; p++) acc[i][p] = 0ull;
    {
        const float* er[2];
#pragma unroll
        for (int i = 0; i < 2; i++) er[i] = sX + (tx + 32 * i) * 132;
#pragma unroll 8
        for (int k0 = 0; k0 < 128; k0 += 4) {
            float4 av[2];
#pragma unroll
            for (int i = 0; i < 2; i++) av[i] = *(const float4*)(er[i] + k0);
#pragma unroll
            for (int kk = 0; kk < 4; kk++) {
                const ulonglong2* bp = w1p + (size_t)(k0 + kk) * 16;
                ulonglong2 b01 = __ldg(bp), b23 = __ldg(bp + 1);
#pragma unroll
                for (int i = 0; i < 2; i++) {
                    float a = ((const float*)&av[i])[kk];
                    u64t ap = pk2(a, a);
                    fma2(acc[i][0], ap, b01.x); fma2(acc[i][1], ap, b01.y);
                    fma2(acc[i][2], ap, b23.x); fma2(acc[i][3], ap, b23.y);
                }
            }
        }
    }
    {
        const float* er[2];
#pragma unroll
        for (int i = 0; i < 2; i++) er[i] = sA + (tx + 32 * i) * 132;
#pragma unroll 8
        for (int k0 = 0; k0 < 128; k0 += 4) {
            float4 av[2];
#pragma unroll
            for (int i = 0; i < 2; i++) av[i] = *(const float4*)(er[i] + k0);
#pragma unroll
            for (int kk = 0; kk < 4; kk++) {
                const ulonglong2* bp = w1p + (size_t)(128 + k0 + kk) * 16;
                ulonglong2 b01 = __ldg(bp), b23 = __ldg(bp + 1);
#pragma unroll
                for (int i = 0; i < 2; i++) {
                    float a = ((const float*)&av[i])[kk];
                    u64t ap = pk2(a, a);
                    fma2(acc[i][0], ap, b01.x); fma2(acc[i][1], ap, b01.y);
                    fma2(acc[i][2], ap, b23.x); fma2(acc[i][3], ap, b23.y);
                }
            }
        }
    }
#pragma unroll
    for (int i = 0; i < 2; i++) {
        int r = tx + 32 * i;
        float* hd = sH + r * 68 + c0;
#pragma unroll
        for (int p = 0; p < 4; p++) {
            float2 v = upk(acc[i][p]);
            hd[2 * p]     = fmaxf(v.x + __ldg(nb1 + c0 + 2 * p), 0.f);
            hd[2 * p + 1] = fmaxf(v.y + __ldg(nb1 + c0 + 2 * p + 1), 0.f);
        }
    }
    __syncthreads();
    {
        const int c1 = ty * 16;
        const ulonglong2* w2p = (const ulonglong2*)(nw2 + c1);
        u64t acc2[2][8];
#pragma unroll
        for (int i = 0; i < 2; i++)
#pragma unroll
            for (int p = 0; p < 8; p++) acc2[i][p] = 0ull;
        const float* hr[2];
#pragma unroll
        for (int i = 0; i < 2; i++) hr[i] = sH + (tx + 32 * i) * 68;
#pragma unroll 4
        for (int k0 = 0; k0 < 64; k0 += 4) {
            float4 av[2];
#pragma unroll
            for (int i = 0; i < 2; i++) av[i] = *(const float4*)(hr[i] + k0);
#pragma unroll
            for (int kk = 0; kk < 4; kk++) {
                const ulonglong2* bp = w2p + (size_t)(k0 + kk) * 32;
                ulonglong2 b01 = __ldg(bp),     b23 = __ldg(bp + 1),
                           b45 = __ldg(bp + 2), b67 = __ldg(bp + 3);
#pragma unroll
                for (int i = 0; i < 2; i++) {
                    float a = ((const float*)&av[i])[kk];
                    u64t ap = pk2(a, a);
                    fma2(acc2[i][0], ap, b01.x); fma2(acc2[i][1], ap, b01.y);
                    fma2(acc2[i][2], ap, b23.x); fma2(acc2[i][3], ap, b23.y);
                    fma2(acc2[i][4], ap, b45.x); fma2(acc2[i][5], ap, b45.y);
                    fma2(acc2[i][6], ap, b67.x); fma2(acc2[i][7], ap, b67.y);
                }
            }
        }
#pragma unroll
        for (int i = 0; i < 2; i++) {
            int r = tx + 32 * i;
            float* xrow = sX + r * 132 + c1;
#pragma unroll
            for (int p = 0; p < 8; p++) {
                float2 v = upk(acc2[i][p]);
                int j = c1 + 2 * p;
                xrow[2 * p]     += v.x + __ldg(nb2 + j);
                xrow[2 * p + 1] += v.y + __ldg(nb2 + j + 1);
            }
        }
    }
    __syncthreads();
    {
        const int r = tid >> 2, qtr = tid & 3;
        const float* rowp = sX + r * 132 + qtr * 32;
        float s = 0.f, s2 = 0.f;
#pragma unroll 8
        for (int k = 0; k < 32; k++) { float t = rowp[k]; s += t; s2 = fmaf(t, t, s2); }
        s  += __shfl_xor_sync(0xffffffffu, s, 1);
        s2 += __shfl_xor_sync(0xffffffffu, s2, 1);
        s  += __shfl_xor_sync(0xffffffffu, s, 2);
        s2 += __shfl_xor_sync(0xffffffffu, s2, 2);
        const float mu  = s * 0.0078125f;
        const float var = fmaf(-mu, mu, s2 * 0.0078125f);
        const float rstd = rsqrtf(var + 1e-5f);
        const int n = n0 + r;
        if (n < NN) {
            float* outp = xout + (size_t)n * 128 + qtr * 32;
#pragma unroll
            for (int q = 0; q < 8; q++) {
                float v0 = rowp[4 * q], v1 = rowp[4 * q + 1];
                float v2 = rowp[4 * q + 2], v3 = rowp[4 * q + 3];
                int j = qtr * 32 + 4 * q;
                float4 o;
                o.x = fmaf((v0 - mu) * rstd, __ldg(nx_g + j),     __ldg(nx_b + j));
                o.y = fmaf((v1 - mu) * rstd, __ldg(nx_g + j + 1), __ldg(nx_b + j + 1));
                o.z = fmaf((v2 - mu) * rstd, __ldg(nx_g + j + 2), __ldg(nx_b + j + 2));
                o.w = fmaf((v3 - mu) * rstd, __ldg(nx_g + j + 3), __ldg(nx_b + j + 3));
                *(float4*)(outp + 4 * q) = o;
            }
        }
    }
}

// --------------------------------- launch ---------------------------------------
extern "C" void kernel_launch(void* const* d_in, const int* in_sizes, int n_in,
                              void* d_out, int out_size) {
    const float* x   = (const float*)d_in[0];
    const void*  ei  = d_in[1];
    const float* ea  = (const float*)d_in[2];
    const float* ew1 = (const float*)d_in[4];
    const float* eb1 = (const float*)d_in[5];
    const float* ew2 = (const float*)d_in[6];
    const float* eb2 = (const float*)d_in[7];
    const float* nw1 = (const float*)d_in[8];
    const float* nb1 = (const float*)d_in[9];
    const float* nw2 = (const float*)d_in[10];
    const float* nb2 = (const float*)d_in[11];
    const float* nxg = (const float*)d_in[12];
    const float* nxb = (const float*)d_in[13];
    const float* neg_ = (const float*)d_in[14];
    const float* neb_ = (const float*)d_in[15];
    float* xout = (float*)d_out;
    float* eout = xout + (size_t)NN * 128;

    const int SM_PRE  = 16896 * 4;   // 67584
    const int SM_EDGE = 25984 * 4;   // 103936
    const int SM_NODE = 21248 * 4;   // 84992
    cudaFuncSetAttribute(k_pre,  cudaFuncAttributeMaxDynamicSharedMemorySize, SM_PRE);
    cudaFuncSetAttribute(k_edge, cudaFuncAttributeMaxDynamicSharedMemorySize, SM_EDGE);
    cudaFuncSetAttribute(k_node, cudaFuncAttributeMaxDynamicSharedMemorySize, SM_NODE);

    k_detect<<<1, 32>>>((const unsigned int*)ei);
    k_zero<<<1024, 256>>>();
    k_pre <<<(NN + 127) / 128, 256, SM_PRE>>>(x, ew1, eb1);
    k_edge<<<NE / 128, 256, SM_EDGE>>>(ea, ei, ew1, ew2, eb2, neg_, neb_, eout);
    k_node<<<(NN + 63) / 64, 256, SM_NODE>>>(x, nw1, nb1, nw2, nb2, nxg, nxb, xout);
}

// round 10
// speedup vs baseline: 1.4408x; 1.3917x over previous
#include <cuda_runtime.h>
#include <cstdint>
#include <cstddef>

#define NN 100000
#define NE 640000

typedef unsigned long long u64t;
typedef unsigned int u32;

__device__ float g_pre[(size_t)NN * 128];
__device__ float g_agg[(size_t)NN * 128];
__device__ float g_cnt[NN];
__device__ int   g_is64;
__device__ u32   g_b1img[8192];   // stage1 B fragments (We^T), tf32, lane-packed
__device__ u32   g_b2img[8192];   // stage2 B fragments (ew2), tf32, lane-packed

// ---------- packed f32x2 helpers (k_pre / k_node) ----------
__device__ __forceinline__ u64t pk2(float lo, float hi) {
    u64t r; asm("mov.b64 %0,{%1,%2};" : "=l"(r) : "f"(lo), "f"(hi)); return r;
}
__device__ __forceinline__ float2 upk(u64t v) {
    float2 r; asm("mov.b64 {%0,%1},%2;" : "=f"(r.x), "=f"(r.y) : "l"(v)); return r;
}
__device__ __forceinline__ void fma2(u64t& d, u64t a, u64t b) {
    asm("fma.rn.f32x2 %0,%1,%2,%0;" : "+l"(d) : "l"(a), "l"(b));
}
__device__ __forceinline__ u32 tf32c(float f) {
    u32 r; asm("cvt.rna.tf32.f32 %0, %1;" : "=r"(r) : "f"(f)); return r;
}
// m16n8k8 tf32 MMA (sm_80+ legacy path; HMMA on sm_100)
__device__ __forceinline__ void mma8(float* c, const u32* a, uint2 b) {
    asm volatile(
        "mma.sync.aligned.m16n8k8.row.col.f32.tf32.tf32.f32 "
        "{%0,%1,%2,%3}, {%4,%5,%6,%7}, {%8,%9}, {%0,%1,%2,%3};"
        : "+f"(c[0]), "+f"(c[1]), "+f"(c[2]), "+f"(c[3])
        : "r"(a[0]), "r"(a[1]), "r"(a[2]), "r"(a[3]), "r"(b.x), "r"(b.y));
}

// ------------------ detect edge_index element width -------------------
__global__ void k_detect(const u32* __restrict__ w) {
    u32 any = 0;
    for (int i = threadIdx.x; i < 1024; i += 32) any |= w[2 * i + 1];
#pragma unroll
    for (int o = 16; o > 0; o >>= 1) any |= __shfl_xor_sync(0xffffffffu, any, o);
    if (threadIdx.x == 0) g_is64 = (any == 0) ? 1 : 0;
}

// ---------------------------- zero scratch ----------------------------
__global__ void k_zero() {
    size_t i = (size_t)blockIdx.x * blockDim.x + threadIdx.x;
    size_t stride = (size_t)gridDim.x * blockDim.x;
    float4* a4 = (float4*)g_agg;
    const size_t n4 = (size_t)NN * 32;
    for (size_t j = i; j < n4; j += stride) a4[j] = make_float4(0.f, 0.f, 0.f, 0.f);
    for (size_t j = i; j < (size_t)NN; j += stride) g_cnt[j] = 0.f;
}

// -------- pack weight fragments (one-time). lane=g*4+t; b0=W[k0+t][n0+g], b1=W[k0+t+4][n0+g]
__global__ void k_prep_w(const float* __restrict__ ew1, const float* __restrict__ ew2) {
    int i = blockIdx.x * 256 + threadIdx.x;    // 0..16383
    if (i < 8192) {        // B1: We[k=128][n=64] = ew1 rows 256..383
        int part = i & 1, idx = i >> 1;
        int lane = idx & 31, kt = (idx >> 5) & 15, nt = idx >> 9;
        int g = lane >> 2, t = lane & 3;
        int k = kt * 8 + t + part * 4, n = nt * 8 + g;
        g_b1img[i] = tf32c(__ldg(ew1 + (size_t)(256 + k) * 64 + n));
    } else {               // B2: ew2[k=64][n=128]
        int j = i - 8192;
        int part = j & 1, idx = j >> 1;
        int lane = idx & 31, kt = (idx >> 5) & 7, nt = idx >> 8;
        int g = lane >> 2, t = lane & 3;
        int k = kt * 8 + t + part * 4, n = nt * 8 + g;
        g_b2img[j] = tf32c(__ldg(ew2 + (size_t)k * 128 + n));
    }
}

// ------------- kernel 1: pre[n] = x @ [Wa|Wb] (+eb1), R8 version ------------
__global__ void __launch_bounds__(256, 2) k_pre(
    const float* __restrict__ x, const float* __restrict__ ew1,
    const float* __restrict__ eb1) {
    extern __shared__ float sm[];
    float* sX = sm;
    const int tid = threadIdx.x;
    const int n0 = blockIdx.x * 128;
#pragma unroll
    for (int it = 0; it < 16; ++it) {
        int idx = tid + it * 256;
        int r = idx >> 5, q = idx & 31;
        int n = n0 + r;
        float4 v = make_float4(0.f, 0.f, 0.f, 0.f);
        if (n < NN) v = __ldg((const float4*)(x + (size_t)n * 128) + q);
        *(float4*)(sX + r * 132 + q * 4) = v;
    }
    __syncthreads();
    const int lane = tid & 31, w = tid >> 5;
    const int wr = w >> 1, wc = w & 1;
    const int rg = lane >> 2, cg = lane & 3;
    const float* wbase = (wc ? ew1 + 8192 : ew1) + cg * 16;
    const ulonglong2* wp = (const ulonglong2*)wbase;
    u64t acc[4][8];
#pragma unroll
    for (int i = 0; i < 4; i++)
#pragma unroll
        for (int p = 0; p < 8; p++) acc[i][p] = 0ull;
    const float* er[4];
#pragma unroll
    for (int i = 0; i < 4; i++) er[i] = sX + (wr * 32 + rg + 8 * i) * 132;
#pragma unroll 4
    for (int k0 = 0; k0 < 128; k0 += 4) {
        float4 av[4];
#pragma unroll
        for (int i = 0; i < 4; i++) av[i] = *(const float4*)(er[i] + k0);
#pragma unroll
        for (int kk = 0; kk < 4; kk++) {
            const ulonglong2* bp = wp + (size_t)(k0 + kk) * 16;
            ulonglong2 b01 = __ldg(bp),     b23 = __ldg(bp + 1),
                       b45 = __ldg(bp + 2), b67 = __ldg(bp + 3);
#pragma unroll
            for (int i = 0; i < 4; i++) {
                float a = ((const float*)&av[i])[kk];
                u64t ap = pk2(a, a);
                fma2(acc[i][0], ap, b01.x); fma2(acc[i][1], ap, b01.y);
                fma2(acc[i][2], ap, b23.x); fma2(acc[i][3], ap, b23.y);
                fma2(acc[i][4], ap, b45.x); fma2(acc[i][5], ap, b45.y);
                fma2(acc[i][6], ap, b67.x); fma2(acc[i][7], ap, b67.y);
            }
        }
    }
    const int ccol = wc * 64 + cg * 16;
#pragma unroll
    for (int i = 0; i < 4; i++) {
        int n = n0 + wr * 32 + rg + 8 * i;
        if (n >= NN) continue;
        float* dst = g_pre + (size_t)n * 128 + ccol;
#pragma unroll
        for (int p = 0; p < 8; p++) {
            float2 v = upk(acc[i][p]);
            if (wc == 0) {
                int j = cg * 16 + 2 * p;
                v.x += __ldg(eb1 + j);
                v.y += __ldg(eb1 + j + 1);
            }
            dst[2 * p] = v.x; dst[2 * p + 1] = v.y;
        }
    }
}

// ------------------- kernel 2: edges via mma.sync tf32 ---------------------
// smem: sCol@0 (512B) | E@1024 (128x132 f32 = 67584) | PAB/H@68608 (128x68 = 34816)
//       B1@103424 (32K) | B2@136192 (32K) -> total 168960. sOut reuses E region.
__global__ void __launch_bounds__(256, 1) k_edge(
    const float* __restrict__ ea, const void* __restrict__ ei_raw,
    const float* __restrict__ eb2, const float* __restrict__ ne_g,
    const float* __restrict__ ne_b, float* __restrict__ eout) {
    extern __shared__ float smf[];
    char* smb = (char*)smf;
    int*   sCol = (int*)smb;
    const int E_B = 1024, PAB_B = 68608, B1_B = 103424, B2_B = 136192;
    u32*   sEu  = (u32*)(smb + E_B);      // tf32, stride 132
    float* sPAB = (float*)(smb + PAB_B);  // fp32, stride 68
    u32*   sHu  = (u32*)(smb + PAB_B);    // tf32 view (phase 2), stride 68
    float* sOut = (float*)(smb + E_B);    // fp32, stride 132 (reuses E)
    const int tid = threadIdx.x;
    const int lane = tid & 31, w = tid >> 5;
    const int g = lane >> 2, t = lane & 3;
    const int e0 = blockIdx.x * 128;
    const int is64 = g_is64;

    if (tid < 128) {
        int c;
        if (is64) c = (int)__ldg(((const long long*)ei_raw) + (size_t)NE + e0 + tid);
        else      c = __ldg(((const int*)ei_raw) + (size_t)NE + e0 + tid);
        sCol[tid] = min(max(c, 0), NN - 1);
    }
    // gather pa[row]+pb[col] (fp32, includes eb1)
#pragma unroll
    for (int it = 0; it < 8; ++it) {
        int idx = tid + it * 256;
        int el = idx >> 4, q = idx & 15;
        int e = e0 + el; int rn, cn;
        if (is64) { const long long* p = (const long long*)ei_raw;
            rn = (int)__ldg(p + e); cn = (int)__ldg(p + (size_t)NE + e); }
        else { const int* p = (const int*)ei_raw;
            rn = __ldg(p + e); cn = __ldg(p + (size_t)NE + e); }
        rn = min(max(rn, 0), NN - 1); cn = min(max(cn, 0), NN - 1);
        float4 va = __ldg((const float4*)(g_pre + (size_t)rn * 128) + q);
        float4 vb = __ldg((const float4*)(g_pre + (size_t)cn * 128) + 16 + q);
        float* d = sPAB + el * 68 + q * 4;
        d[0] = va.x + vb.x; d[1] = va.y + vb.y;
        d[2] = va.z + vb.z; d[3] = va.w + vb.w;
    }
    // E -> smem tf32, row-major stride 132
#pragma unroll
    for (int it = 0; it < 16; ++it) {
        int idx = tid + it * 256;
        int r = idx >> 5, q = idx & 31;
        float4 v = __ldg((const float4*)(ea + (size_t)(e0 + r) * 128) + q);
        uint4 u; u.x = tf32c(v.x); u.y = tf32c(v.y); u.z = tf32c(v.z); u.w = tf32c(v.w);
        *(uint4*)(sEu + r * 132 + q * 4) = u;
    }
    // weight fragment images -> smem
    {
        uint4* b1 = (uint4*)(smb + B1_B);
        uint4* b2 = (uint4*)(smb + B2_B);
        const uint4* s1 = (const uint4*)g_b1img;
        const uint4* s2 = (const uint4*)g_b2img;
#pragma unroll
        for (int it = 0; it < 8; ++it) {
            int i = tid + it * 256;
            b1[i] = __ldg(s1 + i);
            b2[i] = __ldg(s2 + i);
        }
    }
    __syncthreads();

    const int mrow0 = (w & 3) * 32;
    // ---- stage 1: D1[128x64] = E @ We (+PAB in C), warp tile 32x32 ----
    float acc[2][4][4];
    const int nc0s1 = (w >> 2) * 32;
#pragma unroll
    for (int mt = 0; mt < 2; ++mt)
#pragma unroll
        for (int nt = 0; nt < 4; ++nt) {
            int mr = mrow0 + mt * 16 + g;
            int nc = nc0s1 + nt * 8 + 2 * t;
            float2 lo = *(const float2*)(sPAB + mr * 68 + nc);
            float2 hi = *(const float2*)(sPAB + (mr + 8) * 68 + nc);
            acc[mt][nt][0] = lo.x; acc[mt][nt][1] = lo.y;
            acc[mt][nt][2] = hi.x; acc[mt][nt][3] = hi.y;
        }
    __syncthreads();   // all C-inits read PAB before H overwrites it
#pragma unroll
    for (int kt = 0; kt < 16; ++kt) {
        u32 a[2][4];
        const int kc = kt * 8;
#pragma unroll
        for (int mt = 0; mt < 2; ++mt) {
            int base = (mrow0 + mt * 16 + g) * 132 + kc + t;
            a[mt][0] = sEu[base];
            a[mt][1] = sEu[base + 8 * 132];
            a[mt][2] = sEu[base + 4];
            a[mt][3] = sEu[base + 8 * 132 + 4];
        }
#pragma unroll
        for (int nt = 0; nt < 4; ++nt) {
            int ntg = (w >> 2) * 4 + nt;
            uint2 b = *(const uint2*)(smb + B1_B + (((ntg * 16 + kt) * 32 + lane) << 3));
            mma8(acc[0][nt], a[0], b);
            mma8(acc[1][nt], a[1], b);
        }
    }
    // relu + tf32 -> H (overwrites PAB, stride 68)
#pragma unroll
    for (int mt = 0; mt < 2; ++mt)
#pragma unroll
        for (int nt = 0; nt < 4; ++nt) {
            int mr = mrow0 + mt * 16 + g;
            int nc = nc0s1 + nt * 8 + 2 * t;
            uint2 h0, h1;
            h0.x = tf32c(fmaxf(acc[mt][nt][0], 0.f));
            h0.y = tf32c(fmaxf(acc[mt][nt][1], 0.f));
            h1.x = tf32c(fmaxf(acc[mt][nt][2], 0.f));
            h1.y = tf32c(fmaxf(acc[mt][nt][3], 0.f));
            *(uint2*)(sHu + mr * 68 + nc) = h0;
            *(uint2*)(sHu + (mr + 8) * 68 + nc) = h1;
        }
    __syncthreads();
    // ---- stage 2: D2[128x128] = H @ ew2, warp tile 32x64 ----
    float acc2[2][8][4];
#pragma unroll
    for (int mt = 0; mt < 2; ++mt)
#pragma unroll
        for (int nt = 0; nt < 8; ++nt)
#pragma unroll
            for (int p = 0; p < 4; ++p) acc2[mt][nt][p] = 0.f;
    const int nc0s2 = (w >> 2) * 64;
#pragma unroll
    for (int kt = 0; kt < 8; ++kt) {
        u32 a[2][4];
        const int kc = kt * 8;
#pragma unroll
        for (int mt = 0; mt < 2; ++mt) {
            int base = (mrow0 + mt * 16 + g) * 68 + kc + t;
            a[mt][0] = sHu[base];
            a[mt][1] = sHu[base + 8 * 68];
            a[mt][2] = sHu[base + 4];
            a[mt][3] = sHu[base + 8 * 68 + 4];
        }
#pragma unroll
        for (int nt = 0; nt < 8; ++nt) {
            int ntg = (w >> 2) * 8 + nt;
            uint2 b = *(const uint2*)(smb + B2_B + (((ntg * 8 + kt) * 32 + lane) << 3));
            mma8(acc2[0][nt], a[0], b);
            mma8(acc2[1][nt], a[1], b);
        }
    }
    // D2 -> sOut (stride 132; reuses E region — no warp reads sE after stage 1)
#pragma unroll
    for (int mt = 0; mt < 2; ++mt)
#pragma unroll
        for (int nt = 0; nt < 8; ++nt) {
            int mr = mrow0 + mt * 16 + g;
            int nc = nc0s2 + nt * 8 + 2 * t;
            *(float2*)(sOut + mr * 132 + nc)       = make_float2(acc2[mt][nt][0], acc2[mt][nt][1]);
            *(float2*)(sOut + (mr + 8) * 132 + nc) = make_float2(acc2[mt][nt][2], acc2[mt][nt][3]);
        }
    __syncthreads();
    // epilogue: e2 = D2 + e + eb2; scatter; LN -> eout (coalesced, 8 thr/edge)
    {
        const int oct = tid & 7, rs = tid >> 3;
#pragma unroll
        for (int ov = 0; ov < 4; ++ov) {
            int r = ov * 32 + rs;
            float4 vals[4];
            float s = 0.f, s2 = 0.f;
#pragma unroll
            for (int q = 0; q < 4; ++q) {
                int f4 = q * 8 + oct;
                float4 v = *(const float4*)(sOut + r * 132 + f4 * 4);
                float4 e4 = __ldg((const float4*)(ea + (size_t)(e0 + r) * 128) + f4);
                float4 b4 = __ldg((const float4*)eb2 + f4);
                v.x += e4.x + b4.x; v.y += e4.y + b4.y;
                v.z += e4.z + b4.z; v.w += e4.w + b4.w;
                vals[q] = v;
                s += v.x + v.y + v.z + v.w;
                s2 = fmaf(v.x, v.x, s2); s2 = fmaf(v.y, v.y, s2);
                s2 = fmaf(v.z, v.z, s2); s2 = fmaf(v.w, v.w, s2);
            }
            s  += __shfl_xor_sync(0xffffffffu, s, 1);  s2 += __shfl_xor_sync(0xffffffffu, s2, 1);
            s  += __shfl_xor_sync(0xffffffffu, s, 2);  s2 += __shfl_xor_sync(0xffffffffu, s2, 2);
            s  += __shfl_xor_sync(0xffffffffu, s, 4);  s2 += __shfl_xor_sync(0xffffffffu, s2, 4);
            const float mu   = s * 0.0078125f;
            const float var  = fmaf(-mu, mu, s2 * 0.0078125f);
            const float rstd = rsqrtf(var + 1e-5f);
            const int cn = sCol[r];
            float4* aggb = (float4*)(g_agg + (size_t)cn * 128);
            float* outb = eout + (size_t)(e0 + r) * 128;
#pragma unroll
            for (int q = 0; q < 4; ++q) {
                int f4 = q * 8 + oct;
                atomicAdd(aggb + f4, vals[q]);
                int j = f4 * 4;
                float4 o;
                o.x = fmaf((vals[q].x - mu) * rstd, __ldg(ne_g + j),     __ldg(ne_b + j));
                o.y = fmaf((vals[q].y - mu) * rstd, __ldg(ne_g + j + 1), __ldg(ne_b + j + 1));
                o.z = fmaf((vals[q].z - mu) * rstd, __ldg(ne_g + j + 2), __ldg(ne_b + j + 2));
                o.w = fmaf((vals[q].w - mu) * rstd, __ldg(ne_g + j + 3), __ldg(ne_b + j + 3));
                *(float4*)(outb + j) = o;
            }
            if (oct == 0) atomicAdd(g_cnt + cn, 1.0f);
        }
    }
}

// ------------------- kernel 3: nodes (R8 version) ----------------
__global__ void __launch_bounds__(256, 2) k_node(
    const float* __restrict__ x, const float* __restrict__ nw1,
    const float* __restrict__ nb1, const float* __restrict__ nw2,
    const float* __restrict__ nb2, const float* __restrict__ nx_g,
    const float* __restrict__ nx_b, float* __restrict__ xout) {
    extern __shared__ float sm[];
    float* sX = sm;
    float* sA = sm + 8448;
    float* sH = sm + 16896;
    const int tid = threadIdx.x;
    const int n0 = blockIdx.x * 64;
#pragma unroll
    for (int it = 0; it < 8; ++it) {
        int idx = tid + it * 256;
        int r = idx >> 5, q = idx & 31;
        int n = n0 + r;
        float4 v = make_float4(0.f, 0.f, 0.f, 0.f);
        float4 w4 = make_float4(0.f, 0.f, 0.f, 0.f);
        if (n < NN) {
            v = __ldg((const float4*)(x + (size_t)n * 128) + q);
            float c = g_cnt[n];
            float inv = 1.0f / fmaxf(c, 1.0f);
            float4 a = *((const float4*)(g_agg + (size_t)n * 128) + q);
            w4 = make_float4(a.x * inv, a.y * inv, a.z * inv, a.w * inv);
        }
        *(float4*)(sX + r * 132 + q * 4) = v;
        *(float4*)(sA + r * 132 + q * 4) = w4;
    }
    __syncthreads();
    const int tx = tid & 31, ty = tid >> 5;
    const int c0 = ty * 8;
    const ulonglong2* w1p = (const ulonglong2*)(nw1 + c0);
    u64t acc[2][4];
#pragma unroll
    for (int i = 0; i < 2; i++)
#pragma unroll
        for (int p = 0; p < 4; p++) acc[i][p] = 0ull;
    {
        const float* er[2];
#pragma unroll
        for (int i = 0; i < 2; i++) er[i] = sX + (tx + 32 * i) * 132;
#pragma unroll 8
        for (int k0 = 0; k0 < 128; k0 += 4) {
            float4 av[2];
#pragma unroll
            for (int i = 0; i < 2; i++) av[i] = *(const float4*)(er[i] + k0);
#pragma unroll
            for (int kk = 0; kk < 4; kk++) {
                const ulonglong2* bp = w1p + (size_t)(k0 + kk) * 16;
                ulonglong2 b01 = __ldg(bp), b23 = __ldg(bp + 1);
#pragma unroll
                for (int i = 0; i < 2; i++) {
                    float a = ((const float*)&av[i])[kk];
                    u64t ap = pk2(a, a);
                    fma2(acc[i][0], ap, b01.x); fma2(acc[i][1], ap, b01.y);
                    fma2(acc[i][2], ap, b23.x); fma2(acc[i][3], ap, b23.y);
                }
            }
        }
    }
    {
        const float* er[2];
#pragma unroll
        for (int i = 0; i < 2; i++) er[i] = sA + (tx + 32 * i) * 132;
#pragma unroll 8
        for (int k0 = 0; k0 < 128; k0 += 4) {
            float4 av[2];
#pragma unroll
            for (int i = 0; i < 2; i++) av[i] = *(const float4*)(er[i] + k0);
#pragma unroll
            for (int kk = 0; kk < 4; kk++) {
                const ulonglong2* bp = w1p + (size_t)(128 + k0 + kk) * 16;
                ulonglong2 b01 = __ldg(bp), b23 = __ldg(bp + 1);
#pragma unroll
                for (int i = 0; i < 2; i++) {
                    float a = ((const float*)&av[i])[kk];
                    u64t ap = pk2(a, a);
                    fma2(acc[i][0], ap, b01.x); fma2(acc[i][1], ap, b01.y);
                    fma2(acc[i][2], ap, b23.x); fma2(acc[i][3], ap, b23.y);
                }
            }
        }
    }
#pragma unroll
    for (int i = 0; i < 2; i++) {
        int r = tx + 32 * i;
        float* hd = sH + r * 68 + c0;
#pragma unroll
        for (int p = 0; p < 4; p++) {
            float2 v = upk(acc[i][p]);
            hd[2 * p]     = fmaxf(v.x + __ldg(nb1 + c0 + 2 * p), 0.f);
            hd[2 * p + 1] = fmaxf(v.y + __ldg(nb1 + c0 + 2 * p + 1), 0.f);
        }
    }
    __syncthreads();
    {
        const int c1 = ty * 16;
        const ulonglong2* w2p = (const ulonglong2*)(nw2 + c1);
        u64t acc2[2][8];
#pragma unroll
        for (int i = 0; i < 2; i++)
#pragma unroll
            for (int p = 0; p < 8; p++) acc2[i][p] = 0ull;
        const float* hr[2];
#pragma unroll
        for (int i = 0; i < 2; i++) hr[i] = sH + (tx + 32 * i) * 68;
#pragma unroll 4
        for (int k0 = 0; k0 < 64; k0 += 4) {
            float4 av[2];
#pragma unroll
            for (int i = 0; i < 2; i++) av[i] = *(const float4*)(hr[i] + k0);
#pragma unroll
            for (int kk = 0; kk < 4; kk++) {
                const ulonglong2* bp = w2p + (size_t)(k0 + kk) * 32;
                ulonglong2 b01 = __ldg(bp),     b23 = __ldg(bp + 1),
                           b45 = __ldg(bp + 2), b67 = __ldg(bp + 3);
#pragma unroll
                for (int i = 0; i < 2; i++) {
                    float a = ((const float*)&av[i])[kk];
                    u64t ap = pk2(a, a);
                    fma2(acc2[i][0], ap, b01.x); fma2(acc2[i][1], ap, b01.y);
                    fma2(acc2[i][2], ap, b23.x); fma2(acc2[i][3], ap, b23.y);
                    fma2(acc2[i][4], ap, b45.x); fma2(acc2[i][5], ap, b45.y);
                    fma2(acc2[i][6], ap, b67.x); fma2(acc2[i][7], ap, b67.y);
                }
            }
        }
#pragma unroll
        for (int i = 0; i < 2; i++) {
            int r = tx + 32 * i;
            float* xrow = sX + r * 132 + c1;
#pragma unroll
            for (int p = 0; p < 8; p++) {
                float2 v = upk(acc2[i][p]);
                int j = c1 + 2 * p;
                xrow[2 * p]     += v.x + __ldg(nb2 + j);
                xrow[2 * p + 1] += v.y + __ldg(nb2 + j + 1);
            }
        }
    }
    __syncthreads();
    {
        const int r = tid >> 2, qtr = tid & 3;
        const float* rowp = sX + r * 132 + qtr * 32;
        float s = 0.f, s2 = 0.f;
#pragma unroll 8
        for (int k = 0; k < 32; k++) { float tv = rowp[k]; s += tv; s2 = fmaf(tv, tv, s2); }
        s  += __shfl_xor_sync(0xffffffffu, s, 1);
        s2 += __shfl_xor_sync(0xffffffffu, s2, 1);
        s  += __shfl_xor_sync(0xffffffffu, s, 2);
        s2 += __shfl_xor_sync(0xffffffffu, s2, 2);
        const float mu  = s * 0.0078125f;
        const float var = fmaf(-mu, mu, s2 * 0.0078125f);
        const float rstd = rsqrtf(var + 1e-5f);
        const int n = n0 + r;
        if (n < NN) {
            float* outp = xout + (size_t)n * 128 + qtr * 32;
#pragma unroll
            for (int q = 0; q < 8; q++) {
                float v0 = rowp[4 * q], v1 = rowp[4 * q + 1];
                float v2 = rowp[4 * q + 2], v3 = rowp[4 * q + 3];
                int j = qtr * 32 + 4 * q;
                float4 o;
                o.x = fmaf((v0 - mu) * rstd, __ldg(nx_g + j),     __ldg(nx_b + j));
                o.y = fmaf((v1 - mu) * rstd, __ldg(nx_g + j + 1), __ldg(nx_b + j + 1));
                o.z = fmaf((v2 - mu) * rstd, __ldg(nx_g + j + 2), __ldg(nx_b + j + 2));
                o.w = fmaf((v3 - mu) * rstd, __ldg(nx_g + j + 3), __ldg(nx_b + j + 3));
                *(float4*)(outp + 4 * q) = o;
            }
        }
    }
}

// --------------------------------- launch ---------------------------------------
extern "C" void kernel_launch(void* const* d_in, const int* in_sizes, int n_in,
                              void* d_out, int out_size) {
    const float* x   = (const float*)d_in[0];
    const void*  ei  = d_in[1];
    const float* ea  = (const float*)d_in[2];
    const float* ew1 = (const float*)d_in[4];
    const float* eb1 = (const float*)d_in[5];
    const float* ew2 = (const float*)d_in[6];
    const float* eb2 = (const float*)d_in[7];
    const float* nw1 = (const float*)d_in[8];
    const float* nb1 = (const float*)d_in[9];
    const float* nw2 = (const float*)d_in[10];
    const float* nb2 = (const float*)d_in[11];
    const float* nxg = (const float*)d_in[12];
    const float* nxb = (const float*)d_in[13];
    const float* neg_ = (const float*)d_in[14];
    const float* neb_ = (const float*)d_in[15];
    float* xout = (float*)d_out;
    float* eout = xout + (size_t)NN * 128;

    const int SM_PRE  = 16896 * 4;   // 67584
    const int SM_EDGE = 168960;
    const int SM_NODE = 21248 * 4;   // 84992
    cudaFuncSetAttribute(k_pre,  cudaFuncAttributeMaxDynamicSharedMemorySize, SM_PRE);
    cudaFuncSetAttribute(k_edge, cudaFuncAttributeMaxDynamicSharedMemorySize, SM_EDGE);
    cudaFuncSetAttribute(k_node, cudaFuncAttributeMaxDynamicSharedMemorySize, SM_NODE);

    k_detect<<<1, 32>>>((const u32*)ei);
    k_zero<<<1024, 256>>>();
    k_prep_w<<<64, 256>>>(ew1, ew2);
    k_pre <<<(NN + 127) / 128, 256, SM_PRE>>>(x, ew1, eb1);
    k_edge<<<NE / 128, 256, SM_EDGE>>>(ea, ei, eb2, neg_, neb_, eout);
    k_node<<<(NN + 63) / 64, 256, SM_NODE>>>(x, nw1, nb1, nw2, nb2, nxg, nxb, xout);
}

// round 11
// speedup vs baseline: 2.1265x; 1.4759x over previous
#include <cuda_runtime.h>
#include <cstdint>
#include <cstddef>

#define NN 100000
#define NE 640000

typedef unsigned long long u64t;
typedef unsigned int u32;

__device__ float g_pre[(size_t)NN * 128];
__device__ float g_agg[(size_t)NN * 128];
__device__ float g_cnt[NN];
__device__ int   g_is64;
__device__ u32   g_b1img[8192];    // edge stage1 B (We), tf32 lane-packed, Kt=16, Nt=8
__device__ u32   g_b2img[8192];    // edge stage2 B (ew2), Kt=8,  Nt=16
__device__ u32   g_pwimg[16384];   // pre B ([Wa|Wb]),     Kt=16, Nt=16
__device__ u32   g_n1img[16384];   // node stage1 B (nw1), Kt=32, Nt=8
__device__ u32   g_n2img[8192];    // node stage2 B (nw2), Kt=8,  Nt=16

__device__ __forceinline__ u32 tf32c(float f) {
    u32 r; asm("cvt.rna.tf32.f32 %0, %1;" : "=r"(r) : "f"(f)); return r;
}
// m16n8k8 tf32 MMA (sm_80+ legacy path; HMMA on sm_100)
__device__ __forceinline__ void mma8(float* c, const u32* a, uint2 b) {
    asm volatile(
        "mma.sync.aligned.m16n8k8.row.col.f32.tf32.tf32.f32 "
        "{%0,%1,%2,%3}, {%4,%5,%6,%7}, {%8,%9}, {%0,%1,%2,%3};"
        : "+f"(c[0]), "+f"(c[1]), "+f"(c[2]), "+f"(c[3])
        : "r"(a[0]), "r"(a[1]), "r"(a[2]), "r"(a[3]), "r"(b.x), "r"(b.y));
}

// ------------------ detect edge_index element width -------------------
__global__ void k_detect(const u32* __restrict__ w) {
    u32 any = 0;
    for (int i = threadIdx.x; i < 1024; i += 32) any |= w[2 * i + 1];
#pragma unroll
    for (int o = 16; o > 0; o >>= 1) any |= __shfl_xor_sync(0xffffffffu, any, o);
    if (threadIdx.x == 0) g_is64 = (any == 0) ? 1 : 0;
}

// ---------------------------- zero scratch ----------------------------
__global__ void k_zero() {
    size_t i = (size_t)blockIdx.x * blockDim.x + threadIdx.x;
    size_t stride = (size_t)gridDim.x * blockDim.x;
    float4* a4 = (float4*)g_agg;
    const size_t n4 = (size_t)NN * 32;
    for (size_t j = i; j < n4; j += stride) a4[j] = make_float4(0.f, 0.f, 0.f, 0.f);
    for (size_t j = i; j < (size_t)NN; j += stride) g_cnt[j] = 0.f;
}

// -------- pack all weight fragment images (one-time) ----------
// layout: img[((ntg*Kt + kt)*32 + lane)*2 + part] = tf32(W[kt*8 + t + part*4][ntg*8 + g])
__global__ void k_prep_w(const float* __restrict__ ew1, const float* __restrict__ ew2,
                         const float* __restrict__ nw1, const float* __restrict__ nw2) {
    int i = blockIdx.x * 256 + threadIdx.x;   // 0..57343
    if (i < 16384) {                           // g_pwimg: [Wa|Wb], K=128, N=128
        int part = i & 1, idx = i >> 1;
        int lane = idx & 31, kt = (idx >> 5) & 15, ntg = idx >> 9;
        int g = lane >> 2, t = lane & 3;
        int k = kt * 8 + t + part * 4, n = ntg * 8 + g;
        float v = (n < 64) ? __ldg(ew1 + (size_t)k * 64 + n)
                           : __ldg(ew1 + (size_t)(128 + k) * 64 + (n - 64));
        g_pwimg[i] = tf32c(v);
    } else if (i < 24576) {                    // g_b1img: We = ew1 rows 256..383
        int j = i - 16384, part = j & 1, idx = j >> 1;
        int lane = idx & 31, kt = (idx >> 5) & 15, ntg = idx >> 9;
        int g = lane >> 2, t = lane & 3;
        int k = kt * 8 + t + part * 4, n = ntg * 8 + g;
        g_b1img[j] = tf32c(__ldg(ew1 + (size_t)(256 + k) * 64 + n));
    } else if (i < 32768) {                    // g_b2img: ew2, K=64, N=128
        int j = i - 24576, part = j & 1, idx = j >> 1;
        int lane = idx & 31, kt = (idx >> 5) & 7, ntg = idx >> 8;
        int g = lane >> 2, t = lane & 3;
        int k = kt * 8 + t + part * 4, n = ntg * 8 + g;
        g_b2img[j] = tf32c(__ldg(ew2 + (size_t)k * 128 + n));
    } else if (i < 49152) {                    // g_n1img: nw1, K=256, N=64
        int j = i - 32768, part = j & 1, idx = j >> 1;
        int lane = idx & 31, kt = (idx >> 5) & 31, ntg = idx >> 10;
        int g = lane >> 2, t = lane & 3;
        int k = kt * 8 + t + part * 4, n = ntg * 8 + g;
        g_n1img[j] = tf32c(__ldg(nw1 + (size_t)k * 64 + n));
    } else {                                   // g_n2img: nw2, K=64, N=128
        int j = i - 49152, part = j & 1, idx = j >> 1;
        int lane = idx & 31, kt = (idx >> 5) & 7, ntg = idx >> 8;
        int g = lane >> 2, t = lane & 3;
        int k = kt * 8 + t + part * 4, n = ntg * 8 + g;
        g_n2img[j] = tf32c(__ldg(nw2 + (size_t)k * 128 + n));
    }
}

// ------------- kernel 1: pre = x @ [Wa|Wb] (+eb1) via mma.sync -------------
__global__ void __launch_bounds__(256, 2) k_pre(
    const float* __restrict__ x, const float* __restrict__ eb1) {
    extern __shared__ float smf[];
    u32* sXu = (u32*)smf;                     // tf32, stride 132
    const int tid = threadIdx.x;
    const int lane = tid & 31, w = tid >> 5;
    const int g = lane >> 2, t = lane & 3;
    const int n0 = blockIdx.x * 128;

#pragma unroll
    for (int it = 0; it < 16; ++it) {
        int idx = tid + it * 256;
        int r = idx >> 5, q = idx & 31;
        int n = n0 + r;
        float4 v = make_float4(0.f, 0.f, 0.f, 0.f);
        if (n < NN) v = __ldg((const float4*)(x + (size_t)n * 128) + q);
        uint4 u; u.x = tf32c(v.x); u.y = tf32c(v.y); u.z = tf32c(v.z); u.w = tf32c(v.w);
        *(uint4*)(sXu + r * 132 + q * 4) = u;
    }
    __syncthreads();

    const int mrow0 = (w & 3) * 32, wc = w >> 2;
    float acc[2][8][4];
#pragma unroll
    for (int mt = 0; mt < 2; ++mt)
#pragma unroll
        for (int nt = 0; nt < 8; ++nt)
#pragma unroll
            for (int p = 0; p < 4; ++p) acc[mt][nt][p] = 0.f;

#pragma unroll
    for (int kt = 0; kt < 16; ++kt) {
        u32 a[2][4];
        const int kc = kt * 8;
#pragma unroll
        for (int mt = 0; mt < 2; ++mt) {
            int base = (mrow0 + mt * 16 + g) * 132 + kc + t;
            a[mt][0] = sXu[base];
            a[mt][1] = sXu[base + 8 * 132];
            a[mt][2] = sXu[base + 4];
            a[mt][3] = sXu[base + 8 * 132 + 4];
        }
#pragma unroll
        for (int nt = 0; nt < 8; ++nt) {
            int ntg = wc * 8 + nt;
            uint2 b = __ldg((const uint2*)g_pwimg + ((ntg * 16 + kt) * 32 + lane));
            mma8(acc[0][nt], a[0], b);
            mma8(acc[1][nt], a[1], b);
        }
    }
    // epilogue: +eb1 on Wa half, write to g_pre
#pragma unroll
    for (int mt = 0; mt < 2; ++mt)
#pragma unroll
        for (int nt = 0; nt < 8; ++nt) {
            int nc = wc * 64 + nt * 8 + 2 * t;
            float b0 = 0.f, b1v = 0.f;
            if (wc == 0) { b0 = __ldg(eb1 + nc); b1v = __ldg(eb1 + nc + 1); }
            int mr = mrow0 + mt * 16 + g;
            int n1 = n0 + mr, n2 = n0 + mr + 8;
            if (n1 < NN)
                *(float2*)(g_pre + (size_t)n1 * 128 + nc) =
                    make_float2(acc[mt][nt][0] + b0, acc[mt][nt][1] + b1v);
            if (n2 < NN)
                *(float2*)(g_pre + (size_t)n2 * 128 + nc) =
                    make_float2(acc[mt][nt][2] + b0, acc[mt][nt][3] + b1v);
        }
}

// ------------------- kernel 2: edges via mma.sync tf32 (R10, unchanged) ----------
__global__ void __launch_bounds__(256, 1) k_edge(
    const float* __restrict__ ea, const void* __restrict__ ei_raw,
    const float* __restrict__ eb2, const float* __restrict__ ne_g,
    const float* __restrict__ ne_b, float* __restrict__ eout) {
    extern __shared__ float smf[];
    char* smb = (char*)smf;
    int*   sCol = (int*)smb;
    const int E_B = 1024, PAB_B = 68608, B1_B = 103424, B2_B = 136192;
    u32*   sEu  = (u32*)(smb + E_B);
    float* sPAB = (float*)(smb + PAB_B);
    u32*   sHu  = (u32*)(smb + PAB_B);
    float* sOut = (float*)(smb + E_B);
    const int tid = threadIdx.x;
    const int lane = tid & 31, w = tid >> 5;
    const int g = lane >> 2, t = lane & 3;
    const int e0 = blockIdx.x * 128;
    const int is64 = g_is64;

    if (tid < 128) {
        int c;
        if (is64) c = (int)__ldg(((const long long*)ei_raw) + (size_t)NE + e0 + tid);
        else      c = __ldg(((const int*)ei_raw) + (size_t)NE + e0 + tid);
        sCol[tid] = min(max(c, 0), NN - 1);
    }
#pragma unroll
    for (int it = 0; it < 8; ++it) {
        int idx = tid + it * 256;
        int el = idx >> 4, q = idx & 15;
        int e = e0 + el; int rn, cn;
        if (is64) { const long long* p = (const long long*)ei_raw;
            rn = (int)__ldg(p + e); cn = (int)__ldg(p + (size_t)NE + e); }
        else { const int* p = (const int*)ei_raw;
            rn = __ldg(p + e); cn = __ldg(p + (size_t)NE + e); }
        rn = min(max(rn, 0), NN - 1); cn = min(max(cn, 0), NN - 1);
        float4 va = __ldg((const float4*)(g_pre + (size_t)rn * 128) + q);
        float4 vb = __ldg((const float4*)(g_pre + (size_t)cn * 128) + 16 + q);
        float* d = sPAB + el * 68 + q * 4;
        d[0] = va.x + vb.x; d[1] = va.y + vb.y;
        d[2] = va.z + vb.z; d[3] = va.w + vb.w;
    }
#pragma unroll
    for (int it = 0; it < 16; ++it) {
        int idx = tid + it * 256;
        int r = idx >> 5, q = idx & 31;
        float4 v = __ldg((const float4*)(ea + (size_t)(e0 + r) * 128) + q);
        uint4 u; u.x = tf32c(v.x); u.y = tf32c(v.y); u.z = tf32c(v.z); u.w = tf32c(v.w);
        *(uint4*)(sEu + r * 132 + q * 4) = u;
    }
    {
        uint4* b1 = (uint4*)(smb + B1_B);
        uint4* b2 = (uint4*)(smb + B2_B);
        const uint4* s1 = (const uint4*)g_b1img;
        const uint4* s2 = (const uint4*)g_b2img;
#pragma unroll
        for (int it = 0; it < 8; ++it) {
            int i = tid + it * 256;
            b1[i] = __ldg(s1 + i);
            b2[i] = __ldg(s2 + i);
        }
    }
    __syncthreads();

    const int mrow0 = (w & 3) * 32;
    float acc[2][4][4];
    const int nc0s1 = (w >> 2) * 32;
#pragma unroll
    for (int mt = 0; mt < 2; ++mt)
#pragma unroll
        for (int nt = 0; nt < 4; ++nt) {
            int mr = mrow0 + mt * 16 + g;
            int nc = nc0s1 + nt * 8 + 2 * t;
            float2 lo = *(const float2*)(sPAB + mr * 68 + nc);
            float2 hi = *(const float2*)(sPAB + (mr + 8) * 68 + nc);
            acc[mt][nt][0] = lo.x; acc[mt][nt][1] = lo.y;
            acc[mt][nt][2] = hi.x; acc[mt][nt][3] = hi.y;
        }
    __syncthreads();
#pragma unroll
    for (int kt = 0; kt < 16; ++kt) {
        u32 a[2][4];
        const int kc = kt * 8;
#pragma unroll
        for (int mt = 0; mt < 2; ++mt) {
            int base = (mrow0 + mt * 16 + g) * 132 + kc + t;
            a[mt][0] = sEu[base];
            a[mt][1] = sEu[base + 8 * 132];
            a[mt][2] = sEu[base + 4];
            a[mt][3] = sEu[base + 8 * 132 + 4];
        }
#pragma unroll
        for (int nt = 0; nt < 4; ++nt) {
            int ntg = (w >> 2) * 4 + nt;
            uint2 b = *(const uint2*)(smb + B1_B + (((ntg * 16 + kt) * 32 + lane) << 3));
            mma8(acc[0][nt], a[0], b);
            mma8(acc[1][nt], a[1], b);
        }
    }
#pragma unroll
    for (int mt = 0; mt < 2; ++mt)
#pragma unroll
        for (int nt = 0; nt < 4; ++nt) {
            int mr = mrow0 + mt * 16 + g;
            int nc = nc0s1 + nt * 8 + 2 * t;
            uint2 h0, h1;
            h0.x = tf32c(fmaxf(acc[mt][nt][0], 0.f));
            h0.y = tf32c(fmaxf(acc[mt][nt][1], 0.f));
            h1.x = tf32c(fmaxf(acc[mt][nt][2], 0.f));
            h1.y = tf32c(fmaxf(acc[mt][nt][3], 0.f));
            *(uint2*)(sHu + mr * 68 + nc) = h0;
            *(uint2*)(sHu + (mr + 8) * 68 + nc) = h1;
        }
    __syncthreads();
    float acc2[2][8][4];
#pragma unroll
    for (int mt = 0; mt < 2; ++mt)
#pragma unroll
        for (int nt = 0; nt < 8; ++nt)
#pragma unroll
            for (int p = 0; p < 4; ++p) acc2[mt][nt][p] = 0.f;
    const int nc0s2 = (w >> 2) * 64;
#pragma unroll
    for (int kt = 0; kt < 8; ++kt) {
        u32 a[2][4];
        const int kc = kt * 8;
#pragma unroll
        for (int mt = 0; mt < 2; ++mt) {
            int base = (mrow0 + mt * 16 + g) * 68 + kc + t;
            a[mt][0] = sHu[base];
            a[mt][1] = sHu[base + 8 * 68];
            a[mt][2] = sHu[base + 4];
            a[mt][3] = sHu[base + 8 * 68 + 4];
        }
#pragma unroll
        for (int nt = 0; nt < 8; ++nt) {
            int ntg = (w >> 2) * 8 + nt;
            uint2 b = *(const uint2*)(smb + B2_B + (((ntg * 8 + kt) * 32 + lane) << 3));
            mma8(acc2[0][nt], a[0], b);
            mma8(acc2[1][nt], a[1], b);
        }
    }
#pragma unroll
    for (int mt = 0; mt < 2; ++mt)
#pragma unroll
        for (int nt = 0; nt < 8; ++nt) {
            int mr = mrow0 + mt * 16 + g;
            int nc = nc0s2 + nt * 8 + 2 * t;
            *(float2*)(sOut + mr * 132 + nc)       = make_float2(acc2[mt][nt][0], acc2[mt][nt][1]);
            *(float2*)(sOut + (mr + 8) * 132 + nc) = make_float2(acc2[mt][nt][2], acc2[mt][nt][3]);
        }
    __syncthreads();
    {
        const int oct = tid & 7, rs = tid >> 3;
#pragma unroll
        for (int ov = 0; ov < 4; ++ov) {
            int r = ov * 32 + rs;
            float4 vals[4];
            float s = 0.f, s2 = 0.f;
#pragma unroll
            for (int q = 0; q < 4; ++q) {
                int f4 = q * 8 + oct;
                float4 v = *(const float4*)(sOut + r * 132 + f4 * 4);
                float4 e4 = __ldg((const float4*)(ea + (size_t)(e0 + r) * 128) + f4);
                float4 b4 = __ldg((const float4*)eb2 + f4);
                v.x += e4.x + b4.x; v.y += e4.y + b4.y;
                v.z += e4.z + b4.z; v.w += e4.w + b4.w;
                vals[q] = v;
                s += v.x + v.y + v.z + v.w;
                s2 = fmaf(v.x, v.x, s2); s2 = fmaf(v.y, v.y, s2);
                s2 = fmaf(v.z, v.z, s2); s2 = fmaf(v.w, v.w, s2);
            }
            s  += __shfl_xor_sync(0xffffffffu, s, 1);  s2 += __shfl_xor_sync(0xffffffffu, s2, 1);
            s  += __shfl_xor_sync(0xffffffffu, s, 2);  s2 += __shfl_xor_sync(0xffffffffu, s2, 2);
            s  += __shfl_xor_sync(0xffffffffu, s, 4);  s2 += __shfl_xor_sync(0xffffffffu, s2, 4);
            const float mu   = s * 0.0078125f;
            const float var  = fmaf(-mu, mu, s2 * 0.0078125f);
            const float rstd = rsqrtf(var + 1e-5f);
            const int cn = sCol[r];
            float4* aggb = (float4*)(g_agg + (size_t)cn * 128);
            float* outb = eout + (size_t)(e0 + r) * 128;
#pragma unroll
            for (int q = 0; q < 4; ++q) {
                int f4 = q * 8 + oct;
                atomicAdd(aggb + f4, vals[q]);
                int j = f4 * 4;
                float4 o;
                o.x = fmaf((vals[q].x - mu) * rstd, __ldg(ne_g + j),     __ldg(ne_b + j));
                o.y = fmaf((vals[q].y - mu) * rstd, __ldg(ne_g + j + 1), __ldg(ne_b + j + 1));
                o.z = fmaf((vals[q].z - mu) * rstd, __ldg(ne_g + j + 2), __ldg(ne_b + j + 2));
                o.w = fmaf((vals[q].w - mu) * rstd, __ldg(ne_g + j + 3), __ldg(ne_b + j + 3));
                *(float4*)(outb + j) = o;
            }
            if (oct == 0) atomicAdd(g_cnt + cn, 1.0f);
        }
    }
}

// ------------------- kernel 3: nodes via mma.sync tf32 ---------------------
// smem u32 elems: sXu@0 (128*132), sAu@16896 (128*132), sHu@33792 (128*68)
// total 42496 u32 = 169984 B. sOut fp32 reuses sXu region after stage 1.
__global__ void __launch_bounds__(256, 1) k_node(
    const float* __restrict__ x, const float* __restrict__ nb1,
    const float* __restrict__ nb2, const float* __restrict__ nx_g,
    const float* __restrict__ nx_b, float* __restrict__ xout) {
    extern __shared__ float smf[];
    u32* sXu = (u32*)smf;
    u32* sAu = sXu + 16896;
    u32* sHu = sXu + 33792;
    float* sOut = (float*)sXu;                // stride 132 fp32 (phase 2)
    const int tid = threadIdx.x;
    const int lane = tid & 31, w = tid >> 5;
    const int g = lane >> 2, t = lane & 3;
    const int n0 = blockIdx.x * 128;

#pragma unroll
    for (int it = 0; it < 16; ++it) {
        int idx = tid + it * 256;
        int r = idx >> 5, q = idx & 31;
        int n = n0 + r;
        float4 v = make_float4(0.f, 0.f, 0.f, 0.f);
        float4 a = make_float4(0.f, 0.f, 0.f, 0.f);
        if (n < NN) {
            v = __ldg((const float4*)(x + (size_t)n * 128) + q);
            float c = g_cnt[n];
            float inv = 1.0f / fmaxf(c, 1.0f);
            float4 ag = *((const float4*)(g_agg + (size_t)n * 128) + q);
            a = make_float4(ag.x * inv, ag.y * inv, ag.z * inv, ag.w * inv);
        }
        uint4 ux; ux.x = tf32c(v.x); ux.y = tf32c(v.y); ux.z = tf32c(v.z); ux.w = tf32c(v.w);
        uint4 ua; ua.x = tf32c(a.x); ua.y = tf32c(a.y); ua.z = tf32c(a.z); ua.w = tf32c(a.w);
        *(uint4*)(sXu + r * 132 + q * 4) = ux;
        *(uint4*)(sAu + r * 132 + q * 4) = ua;
    }
    __syncthreads();

    const int mrow0 = (w & 3) * 32;
    // stage 1: H[128x64] = [x|agg] @ nw1, K=256 (kt<16: x, kt>=16: agg)
    float acc[2][4][4];
#pragma unroll
    for (int mt = 0; mt < 2; ++mt)
#pragma unroll
        for (int nt = 0; nt < 4; ++nt)
#pragma unroll
            for (int p = 0; p < 4; ++p) acc[mt][nt][p] = 0.f;
    const int nc0s1 = (w >> 2) * 32;
#pragma unroll
    for (int kt = 0; kt < 32; ++kt) {
        const u32* src = (kt < 16) ? sXu : sAu;
        const int kc = (kt & 15) * 8;
        u32 a[2][4];
#pragma unroll
        for (int mt = 0; mt < 2; ++mt) {
            int base = (mrow0 + mt * 16 + g) * 132 + kc + t;
            a[mt][0] = src[base];
            a[mt][1] = src[base + 8 * 132];
            a[mt][2] = src[base + 4];
            a[mt][3] = src[base + 8 * 132 + 4];
        }
#pragma unroll
        for (int nt = 0; nt < 4; ++nt) {
            int ntg = (w >> 2) * 4 + nt;
            uint2 b = __ldg((const uint2*)g_n1img + ((ntg * 32 + kt) * 32 + lane));
            mma8(acc[0][nt], a[0], b);
            mma8(acc[1][nt], a[1], b);
        }
    }
    // relu(acc + nb1) -> H tf32 (stride 68)
#pragma unroll
    for (int mt = 0; mt < 2; ++mt)
#pragma unroll
        for (int nt = 0; nt < 4; ++nt) {
            int mr = mrow0 + mt * 16 + g;
            int nc = nc0s1 + nt * 8 + 2 * t;
            float b0 = __ldg(nb1 + nc), b1v = __ldg(nb1 + nc + 1);
            uint2 h0, h1;
            h0.x = tf32c(fmaxf(acc[mt][nt][0] + b0, 0.f));
            h0.y = tf32c(fmaxf(acc[mt][nt][1] + b1v, 0.f));
            h1.x = tf32c(fmaxf(acc[mt][nt][2] + b0, 0.f));
            h1.y = tf32c(fmaxf(acc[mt][nt][3] + b1v, 0.f));
            *(uint2*)(sHu + mr * 68 + nc) = h0;
            *(uint2*)(sHu + (mr + 8) * 68 + nc) = h1;
        }
    __syncthreads();
    // stage 2: D2[128x128] = H @ nw2
    float acc2[2][8][4];
#pragma unroll
    for (int mt = 0; mt < 2; ++mt)
#pragma unroll
        for (int nt = 0; nt < 8; ++nt)
#pragma unroll
            for (int p = 0; p < 4; ++p) acc2[mt][nt][p] = 0.f;
    const int nc0s2 = (w >> 2) * 64;
#pragma unroll
    for (int kt = 0; kt < 8; ++kt) {
        u32 a[2][4];
        const int kc = kt * 8;
#pragma unroll
        for (int mt = 0; mt < 2; ++mt) {
            int base = (mrow0 + mt * 16 + g) * 68 + kc + t;
            a[mt][0] = sHu[base];
            a[mt][1] = sHu[base + 8 * 68];
            a[mt][2] = sHu[base + 4];
            a[mt][3] = sHu[base + 8 * 68 + 4];
        }
#pragma unroll
        for (int nt = 0; nt < 8; ++nt) {
            int ntg = (w >> 2) * 8 + nt;
            uint2 b = __ldg((const uint2*)g_n2img + ((ntg * 8 + kt) * 32 + lane));
            mma8(acc2[0][nt], a[0], b);
            mma8(acc2[1][nt], a[1], b);
        }
    }
    // D2 -> sOut (reuses sXu region; stage1 reads completed before H-sync)
#pragma unroll
    for (int mt = 0; mt < 2; ++mt)
#pragma unroll
        for (int nt = 0; nt < 8; ++nt) {
            int mr = mrow0 + mt * 16 + g;
            int nc = nc0s2 + nt * 8 + 2 * t;
            *(float2*)(sOut + mr * 132 + nc)       = make_float2(acc2[mt][nt][0], acc2[mt][nt][1]);
            *(float2*)(sOut + (mr + 8) * 132 + nc) = make_float2(acc2[mt][nt][2], acc2[mt][nt][3]);
        }
    __syncthreads();
    // epilogue: x2 = D2 + x + nb2; LN -> xout (coalesced, 8 thr/row)
    {
        const int oct = tid & 7, rs = tid >> 3;
#pragma unroll
        for (int ov = 0; ov < 4; ++ov) {
            int r = ov * 32 + rs;
            int n = n0 + r;
            int nld = min(n, NN - 1);
            float4 vals[4];
            float s = 0.f, s2 = 0.f;
#pragma unroll
            for (int q = 0; q < 4; ++q) {
                int f4 = q * 8 + oct;
                float4 v = *(const float4*)(sOut + r * 132 + f4 * 4);
                float4 x4 = __ldg((const float4*)(x + (size_t)nld * 128) + f4);
                float4 b4 = __ldg((const float4*)nb2 + f4);
                v.x += x4.x + b4.x; v.y += x4.y + b4.y;
                v.z += x4.z + b4.z; v.w += x4.w + b4.w;
                vals[q] = v;
                s += v.x + v.y + v.z + v.w;
                s2 = fmaf(v.x, v.x, s2); s2 = fmaf(v.y, v.y, s2);
                s2 = fmaf(v.z, v.z, s2); s2 = fmaf(v.w, v.w, s2);
            }
            s  += __shfl_xor_sync(0xffffffffu, s, 1);  s2 += __shfl_xor_sync(0xffffffffu, s2, 1);
            s  += __shfl_xor_sync(0xffffffffu, s, 2);  s2 += __shfl_xor_sync(0xffffffffu, s2, 2);
            s  += __shfl_xor_sync(0xffffffffu, s, 4);  s2 += __shfl_xor_sync(0xffffffffu, s2, 4);
            const float mu   = s * 0.0078125f;
            const float var  = fmaf(-mu, mu, s2 * 0.0078125f);
            const float rstd = rsqrtf(var + 1e-5f);
            if (n < NN) {
                float* outb = xout + (size_t)n * 128;
#pragma unroll
                for (int q = 0; q < 4; ++q) {
                    int f4 = q * 8 + oct;
                    int j = f4 * 4;
                    float4 o;
                    o.x = fmaf((vals[q].x - mu) * rstd, __ldg(nx_g + j),     __ldg(nx_b + j));
                    o.y = fmaf((vals[q].y - mu) * rstd, __ldg(nx_g + j + 1), __ldg(nx_b + j + 1));
                    o.z = fmaf((vals[q].z - mu) * rstd, __ldg(nx_g + j + 2), __ldg(nx_b + j + 2));
                    o.w = fmaf((vals[q].w - mu) * rstd, __ldg(nx_g + j + 3), __ldg(nx_b + j + 3));
                    *(float4*)(outb + j) = o;
                }
            }
        }
    }
}

// --------------------------------- launch ---------------------------------------
extern "C" void kernel_launch(void* const* d_in, const int* in_sizes, int n_in,
                              void* d_out, int out_size) {
    const float* x   = (const float*)d_in[0];
    const void*  ei  = d_in[1];
    const float* ea  = (const float*)d_in[2];
    const float* ew1 = (const float*)d_in[4];
    const float* eb1 = (const float*)d_in[5];
    const float* ew2 = (const float*)d_in[6];
    const float* eb2 = (const float*)d_in[7];
    const float* nw1 = (const float*)d_in[8];
    const float* nb1 = (const float*)d_in[9];
    const float* nw2 = (const float*)d_in[10];
    const float* nb2 = (const float*)d_in[11];
    const float* nxg = (const float*)d_in[12];
    const float* nxb = (const float*)d_in[13];
    const float* neg_ = (const float*)d_in[14];
    const float* neb_ = (const float*)d_in[15];
    float* xout = (float*)d_out;
    float* eout = xout + (size_t)NN * 128;

    const int SM_PRE  = 67584;
    const int SM_EDGE = 168960;
    const int SM_NODE = 169984;
    cudaFuncSetAttribute(k_pre,  cudaFuncAttributeMaxDynamicSharedMemorySize, SM_PRE);
    cudaFuncSetAttribute(k_edge, cudaFuncAttributeMaxDynamicSharedMemorySize, SM_EDGE);
    cudaFuncSetAttribute(k_node, cudaFuncAttributeMaxDynamicSharedMemorySize, SM_NODE);

    k_detect<<<1, 32>>>((const u32*)ei);
    k_zero<<<1024, 256>>>();
    k_prep_w<<<224, 256>>>(ew1, ew2, nw1, nw2);
    k_pre <<<(NN + 127) / 128, 256, SM_PRE>>>(x, eb1);
    k_edge<<<NE / 128, 256, SM_EDGE>>>(ea, ei, eb2, neg_, neb_, eout);
    k_node<<<(NN + 127) / 128, 256, SM_NODE>>>(x, nb1, nb2, nxg, nxb, xout);
}

// round 12
// speedup vs baseline: 2.3666x; 1.1129x over previous
#include <cuda_runtime.h>
#include <cstdint>
#include <cstddef>

#define NN 100000
#define NE 640000

typedef unsigned long long u64t;
typedef unsigned int u32;

__device__ float g_pre[(size_t)NN * 128];
__device__ float g_agg[(size_t)NN * 128];
__device__ float g_cnt[NN];
__device__ int   g_is64;
__device__ u32   g_b1img[8192];    // edge stage1 B (We), tf32 lane-packed, Kt=16, Nt=8
__device__ u32   g_b2img[8192];    // edge stage2 B (ew2), Kt=8,  Nt=16
__device__ u32   g_pwimg[16384];   // pre B ([Wa|Wb]),     Kt=16, Nt=16
__device__ u32   g_n1img[16384];   // node stage1 B (nw1), Kt=32, Nt=8
__device__ u32   g_n2img[8192];    // node stage2 B (nw2), Kt=8,  Nt=16

__device__ __forceinline__ u32 tf32c(float f) {
    u32 r; asm("cvt.rna.tf32.f32 %0, %1;" : "=r"(r) : "f"(f)); return r;
}
// m16n8k8 tf32 MMA (sm_80+ legacy path; HMMA on sm_100)
__device__ __forceinline__ void mma8(float* c, const u32* a, uint2 b) {
    asm volatile(
        "mma.sync.aligned.m16n8k8.row.col.f32.tf32.tf32.f32 "
        "{%0,%1,%2,%3}, {%4,%5,%6,%7}, {%8,%9}, {%0,%1,%2,%3};"
        : "+f"(c[0]), "+f"(c[1]), "+f"(c[2]), "+f"(c[3])
        : "r"(a[0]), "r"(a[1]), "r"(a[2]), "r"(a[3]), "r"(b.x), "r"(b.y));
}

// ------------------ detect edge_index element width -------------------
__global__ void k_detect(const u32* __restrict__ w) {
    u32 any = 0;
    for (int i = threadIdx.x; i < 1024; i += 32) any |= w[2 * i + 1];
#pragma unroll
    for (int o = 16; o > 0; o >>= 1) any |= __shfl_xor_sync(0xffffffffu, any, o);
    if (threadIdx.x == 0) g_is64 = (any == 0) ? 1 : 0;
}

// ---------------------------- zero scratch ----------------------------
__global__ void k_zero() {
    size_t i = (size_t)blockIdx.x * blockDim.x + threadIdx.x;
    size_t stride = (size_t)gridDim.x * blockDim.x;
    float4* a4 = (float4*)g_agg;
    const size_t n4 = (size_t)NN * 32;
    for (size_t j = i; j < n4; j += stride) a4[j] = make_float4(0.f, 0.f, 0.f, 0.f);
    for (size_t j = i; j < (size_t)NN; j += stride) g_cnt[j] = 0.f;
}

// -------- pack all weight fragment images (one-time) ----------
// layout: img[((ntg*Kt + kt)*32 + lane)*2 + part] = tf32(W[kt*8 + t + part*4][ntg*8 + g])
__global__ void k_prep_w(const float* __restrict__ ew1, const float* __restrict__ ew2,
                         const float* __restrict__ nw1, const float* __restrict__ nw2) {
    int i = blockIdx.x * 256 + threadIdx.x;   // 0..57343
    if (i < 16384) {                           // g_pwimg: [Wa|Wb], K=128, N=128
        int part = i & 1, idx = i >> 1;
        int lane = idx & 31, kt = (idx >> 5) & 15, ntg = idx >> 9;
        int g = lane >> 2, t = lane & 3;
        int k = kt * 8 + t + part * 4, n = ntg * 8 + g;
        float v = (n < 64) ? __ldg(ew1 + (size_t)k * 64 + n)
                           : __ldg(ew1 + (size_t)(128 + k) * 64 + (n - 64));
        g_pwimg[i] = tf32c(v);
    } else if (i < 24576) {                    // g_b1img: We = ew1 rows 256..383
        int j = i - 16384, part = j & 1, idx = j >> 1;
        int lane = idx & 31, kt = (idx >> 5) & 15, ntg = idx >> 9;
        int g = lane >> 2, t = lane & 3;
        int k = kt * 8 + t + part * 4, n = ntg * 8 + g;
        g_b1img[j] = tf32c(__ldg(ew1 + (size_t)(256 + k) * 64 + n));
    } else if (i < 32768) {                    // g_b2img: ew2, K=64, N=128
        int j = i - 24576, part = j & 1, idx = j >> 1;
        int lane = idx & 31, kt = (idx >> 5) & 7, ntg = idx >> 8;
        int g = lane >> 2, t = lane & 3;
        int k = kt * 8 + t + part * 4, n = ntg * 8 + g;
        g_b2img[j] = tf32c(__ldg(ew2 + (size_t)k * 128 + n));
    } else if (i < 49152) {                    // g_n1img: nw1, K=256, N=64
        int j = i - 32768, part = j & 1, idx = j >> 1;
        int lane = idx & 31, kt = (idx >> 5) & 31, ntg = idx >> 10;
        int g = lane >> 2, t = lane & 3;
        int k = kt * 8 + t + part * 4, n = ntg * 8 + g;
        g_n1img[j] = tf32c(__ldg(nw1 + (size_t)k * 64 + n));
    } else {                                   // g_n2img: nw2, K=64, N=128
        int j = i - 49152, part = j & 1, idx = j >> 1;
        int lane = idx & 31, kt = (idx >> 5) & 7, ntg = idx >> 8;
        int g = lane >> 2, t = lane & 3;
        int k = kt * 8 + t + part * 4, n = ntg * 8 + g;
        g_n2img[j] = tf32c(__ldg(nw2 + (size_t)k * 128 + n));
    }
}

// ------------- kernel 1: pre = x @ [Wa|Wb] (+eb1) via mma.sync -------------
__global__ void __launch_bounds__(256, 2) k_pre(
    const float* __restrict__ x, const float* __restrict__ eb1) {
    extern __shared__ float smf[];
    u32* sXu = (u32*)smf;                     // tf32, stride 132
    const int tid = threadIdx.x;
    const int lane = tid & 31, w = tid >> 5;
    const int g = lane >> 2, t = lane & 3;
    const int n0 = blockIdx.x * 128;

#pragma unroll
    for (int it = 0; it < 16; ++it) {
        int idx = tid + it * 256;
        int r = idx >> 5, q = idx & 31;
        int n = n0 + r;
        float4 v = make_float4(0.f, 0.f, 0.f, 0.f);
        if (n < NN) v = __ldg((const float4*)(x + (size_t)n * 128) + q);
        uint4 u; u.x = tf32c(v.x); u.y = tf32c(v.y); u.z = tf32c(v.z); u.w = tf32c(v.w);
        *(uint4*)(sXu + r * 132 + q * 4) = u;
    }
    __syncthreads();

    const int mrow0 = (w & 3) * 32, wc = w >> 2;
    float acc[2][8][4];
#pragma unroll
    for (int mt = 0; mt < 2; ++mt)
#pragma unroll
        for (int nt = 0; nt < 8; ++nt)
#pragma unroll
            for (int p = 0; p < 4; ++p) acc[mt][nt][p] = 0.f;

#pragma unroll
    for (int kt = 0; kt < 16; ++kt) {
        u32 a[2][4];
        const int kc = kt * 8;
#pragma unroll
        for (int mt = 0; mt < 2; ++mt) {
            int base = (mrow0 + mt * 16 + g) * 132 + kc + t;
            a[mt][0] = sXu[base];
            a[mt][1] = sXu[base + 8 * 132];
            a[mt][2] = sXu[base + 4];
            a[mt][3] = sXu[base + 8 * 132 + 4];
        }
#pragma unroll
        for (int nt = 0; nt < 8; ++nt) {
            int ntg = wc * 8 + nt;
            uint2 b = __ldg((const uint2*)g_pwimg + ((ntg * 16 + kt) * 32 + lane));
            mma8(acc[0][nt], a[0], b);
            mma8(acc[1][nt], a[1], b);
        }
    }
    // epilogue: +eb1 on Wa half, write to g_pre
#pragma unroll
    for (int mt = 0; mt < 2; ++mt)
#pragma unroll
        for (int nt = 0; nt < 8; ++nt) {
            int nc = wc * 64 + nt * 8 + 2 * t;
            float b0 = 0.f, b1v = 0.f;
            if (wc == 0) { b0 = __ldg(eb1 + nc); b1v = __ldg(eb1 + nc + 1); }
            int mr = mrow0 + mt * 16 + g;
            int n1 = n0 + mr, n2 = n0 + mr + 8;
            if (n1 < NN)
                *(float2*)(g_pre + (size_t)n1 * 128 + nc) =
                    make_float2(acc[mt][nt][0] + b0, acc[mt][nt][1] + b1v);
            if (n2 < NN)
                *(float2*)(g_pre + (size_t)n2 * 128 + nc) =
                    make_float2(acc[mt][nt][2] + b0, acc[mt][nt][3] + b1v);
        }
}

// ------------------- kernel 2: edges via mma.sync tf32, B from L2, 2 CTAs/SM ----
// smem: sCol@0 (1024B) | E@1024 (128x132 u32 = 67584) | PAB/H@68608 (128x68 = 34816)
// total 103424 B -> 2 CTAs/SM. sOut fp32 reuses E region after stage 1.
__global__ void __launch_bounds__(256, 2) k_edge(
    const float* __restrict__ ea, const void* __restrict__ ei_raw,
    const float* __restrict__ eb2, const float* __restrict__ ne_g,
    const float* __restrict__ ne_b, float* __restrict__ eout) {
    extern __shared__ float smf[];
    char* smb = (char*)smf;
    int*   sCol = (int*)smb;
    const int E_B = 1024, PAB_B = 68608;
    u32*   sEu  = (u32*)(smb + E_B);
    float* sPAB = (float*)(smb + PAB_B);
    u32*   sHu  = (u32*)(smb + PAB_B);
    float* sOut = (float*)(smb + E_B);
    const int tid = threadIdx.x;
    const int lane = tid & 31, w = tid >> 5;
    const int g = lane >> 2, t = lane & 3;
    const int e0 = blockIdx.x * 128;
    const int is64 = g_is64;

    if (tid < 128) {
        int c;
        if (is64) c = (int)__ldg(((const long long*)ei_raw) + (size_t)NE + e0 + tid);
        else      c = __ldg(((const int*)ei_raw) + (size_t)NE + e0 + tid);
        sCol[tid] = min(max(c, 0), NN - 1);
    }
    // gather pa[row]+pb[col] (fp32)
#pragma unroll
    for (int it = 0; it < 8; ++it) {
        int idx = tid + it * 256;
        int el = idx >> 4, q = idx & 15;
        int e = e0 + el; int rn, cn;
        if (is64) { const long long* p = (const long long*)ei_raw;
            rn = (int)__ldg(p + e); cn = (int)__ldg(p + (size_t)NE + e); }
        else { const int* p = (const int*)ei_raw;
            rn = __ldg(p + e); cn = __ldg(p + (size_t)NE + e); }
        rn = min(max(rn, 0), NN - 1); cn = min(max(cn, 0), NN - 1);
        float4 va = __ldg((const float4*)(g_pre + (size_t)rn * 128) + q);
        float4 vb = __ldg((const float4*)(g_pre + (size_t)cn * 128) + 16 + q);
        float* d = sPAB + el * 68 + q * 4;
        d[0] = va.x + vb.x; d[1] = va.y + vb.y;
        d[2] = va.z + vb.z; d[3] = va.w + vb.w;
    }
    // E -> smem tf32, stride 132
#pragma unroll
    for (int it = 0; it < 16; ++it) {
        int idx = tid + it * 256;
        int r = idx >> 5, q = idx & 31;
        float4 v = __ldg((const float4*)(ea + (size_t)(e0 + r) * 128) + q);
        uint4 u; u.x = tf32c(v.x); u.y = tf32c(v.y); u.z = tf32c(v.z); u.w = tf32c(v.w);
        *(uint4*)(sEu + r * 132 + q * 4) = u;
    }
    __syncthreads();

    const int mrow0 = (w & 3) * 32;
    // stage 1: D1[128x64] = E @ We (+PAB in C), warp tile 32x32
    float acc[2][4][4];
    const int nc0s1 = (w >> 2) * 32;
#pragma unroll
    for (int mt = 0; mt < 2; ++mt)
#pragma unroll
        for (int nt = 0; nt < 4; ++nt) {
            int mr = mrow0 + mt * 16 + g;
            int nc = nc0s1 + nt * 8 + 2 * t;
            float2 lo = *(const float2*)(sPAB + mr * 68 + nc);
            float2 hi = *(const float2*)(sPAB + (mr + 8) * 68 + nc);
            acc[mt][nt][0] = lo.x; acc[mt][nt][1] = lo.y;
            acc[mt][nt][2] = hi.x; acc[mt][nt][3] = hi.y;
        }
    __syncthreads();   // all C-inits read PAB before H overwrites it
#pragma unroll
    for (int kt = 0; kt < 16; ++kt) {
        u32 a[2][4];
        const int kc = kt * 8;
#pragma unroll
        for (int mt = 0; mt < 2; ++mt) {
            int base = (mrow0 + mt * 16 + g) * 132 + kc + t;
            a[mt][0] = sEu[base];
            a[mt][1] = sEu[base + 8 * 132];
            a[mt][2] = sEu[base + 4];
            a[mt][3] = sEu[base + 8 * 132 + 4];
        }
#pragma unroll
        for (int nt = 0; nt < 4; ++nt) {
            int ntg = (w >> 2) * 4 + nt;
            uint2 b = __ldg((const uint2*)g_b1img + ((ntg * 16 + kt) * 32 + lane));
            mma8(acc[0][nt], a[0], b);
            mma8(acc[1][nt], a[1], b);
        }
    }
    // relu + tf32 -> H (overwrites PAB, stride 68)
#pragma unroll
    for (int mt = 0; mt < 2; ++mt)
#pragma unroll
        for (int nt = 0; nt < 4; ++nt) {
            int mr = mrow0 + mt * 16 + g;
            int nc = nc0s1 + nt * 8 + 2 * t;
            uint2 h0, h1;
            h0.x = tf32c(fmaxf(acc[mt][nt][0], 0.f));
            h0.y = tf32c(fmaxf(acc[mt][nt][1], 0.f));
            h1.x = tf32c(fmaxf(acc[mt][nt][2], 0.f));
            h1.y = tf32c(fmaxf(acc[mt][nt][3], 0.f));
            *(uint2*)(sHu + mr * 68 + nc) = h0;
            *(uint2*)(sHu + (mr + 8) * 68 + nc) = h1;
        }
    __syncthreads();
    // stage 2: D2[128x128] = H @ ew2, warp tile 32x64
    float acc2[2][8][4];
#pragma unroll
    for (int mt = 0; mt < 2; ++mt)
#pragma unroll
        for (int nt = 0; nt < 8; ++nt)
#pragma unroll
            for (int p = 0; p < 4; ++p) acc2[mt][nt][p] = 0.f;
    const int nc0s2 = (w >> 2) * 64;
#pragma unroll
    for (int kt = 0; kt < 8; ++kt) {
        u32 a[2][4];
        const int kc = kt * 8;
#pragma unroll
        for (int mt = 0; mt < 2; ++mt) {
            int base = (mrow0 + mt * 16 + g) * 68 + kc + t;
            a[mt][0] = sHu[base];
            a[mt][1] = sHu[base + 8 * 68];
            a[mt][2] = sHu[base + 4];
            a[mt][3] = sHu[base + 8 * 68 + 4];
        }
#pragma unroll
        for (int nt = 0; nt < 8; ++nt) {
            int ntg = (w >> 2) * 8 + nt;
            uint2 b = __ldg((const uint2*)g_b2img + ((ntg * 8 + kt) * 32 + lane));
            mma8(acc2[0][nt], a[0], b);
            mma8(acc2[1][nt], a[1], b);
        }
    }
    // D2 -> sOut (stride 132; reuses E region)
#pragma unroll
    for (int mt = 0; mt < 2; ++mt)
#pragma unroll
        for (int nt = 0; nt < 8; ++nt) {
            int mr = mrow0 + mt * 16 + g;
            int nc = nc0s2 + nt * 8 + 2 * t;
            *(float2*)(sOut + mr * 132 + nc)       = make_float2(acc2[mt][nt][0], acc2[mt][nt][1]);
            *(float2*)(sOut + (mr + 8) * 132 + nc) = make_float2(acc2[mt][nt][2], acc2[mt][nt][3]);
        }
    __syncthreads();
    // epilogue: e2 = D2 + e + eb2; scatter; LN -> eout (coalesced, 8 thr/edge)
    {
        const int oct = tid & 7, rs = tid >> 3;
#pragma unroll
        for (int ov = 0; ov < 4; ++ov) {
            int r = ov * 32 + rs;
            float4 vals[4];
            float s = 0.f, s2 = 0.f;
#pragma unroll
            for (int q = 0; q < 4; ++q) {
                int f4 = q * 8 + oct;
                float4 v = *(const float4*)(sOut + r * 132 + f4 * 4);
                float4 e4 = __ldg((const float4*)(ea + (size_t)(e0 + r) * 128) + f4);
                float4 b4 = __ldg((const float4*)eb2 + f4);
                v.x += e4.x + b4.x; v.y += e4.y + b4.y;
                v.z += e4.z + b4.z; v.w += e4.w + b4.w;
                vals[q] = v;
                s += v.x + v.y + v.z + v.w;
                s2 = fmaf(v.x, v.x, s2); s2 = fmaf(v.y, v.y, s2);
                s2 = fmaf(v.z, v.z, s2); s2 = fmaf(v.w, v.w, s2);
            }
            s  += __shfl_xor_sync(0xffffffffu, s, 1);  s2 += __shfl_xor_sync(0xffffffffu, s2, 1);
            s  += __shfl_xor_sync(0xffffffffu, s, 2);  s2 += __shfl_xor_sync(0xffffffffu, s2, 2);
            s  += __shfl_xor_sync(0xffffffffu, s, 4);  s2 += __shfl_xor_sync(0xffffffffu, s2, 4);
            const float mu   = s * 0.0078125f;
            const float var  = fmaf(-mu, mu, s2 * 0.0078125f);
            const float rstd = rsqrtf(var + 1e-5f);
            const int cn = sCol[r];
            float4* aggb = (float4*)(g_agg + (size_t)cn * 128);
            float* outb = eout + (size_t)(e0 + r) * 128;
#pragma unroll
            for (int q = 0; q < 4; ++q) {
                int f4 = q * 8 + oct;
                atomicAdd(aggb + f4, vals[q]);
                int j = f4 * 4;
                float4 o;
                o.x = fmaf((vals[q].x - mu) * rstd, __ldg(ne_g + j),     __ldg(ne_b + j));
                o.y = fmaf((vals[q].y - mu) * rstd, __ldg(ne_g + j + 1), __ldg(ne_b + j + 1));
                o.z = fmaf((vals[q].z - mu) * rstd, __ldg(ne_g + j + 2), __ldg(ne_b + j + 2));
                o.w = fmaf((vals[q].w - mu) * rstd, __ldg(ne_g + j + 3), __ldg(ne_b + j + 3));
                *(float4*)(outb + j) = o;
            }
            if (oct == 0) atomicAdd(g_cnt + cn, 1.0f);
        }
    }
}

// ------------------- kernel 3: nodes via mma.sync tf32 (R11, unchanged) ----------
__global__ void __launch_bounds__(256, 1) k_node(
    const float* __restrict__ x, const float* __restrict__ nb1,
    const float* __restrict__ nb2, const float* __restrict__ nx_g,
    const float* __restrict__ nx_b, float* __restrict__ xout) {
    extern __shared__ float smf[];
    u32* sXu = (u32*)smf;
    u32* sAu = sXu + 16896;
    u32* sHu = sXu + 33792;
    float* sOut = (float*)sXu;
    const int tid = threadIdx.x;
    const int lane = tid & 31, w = tid >> 5;
    const int g = lane >> 2, t = lane & 3;
    const int n0 = blockIdx.x * 128;

#pragma unroll
    for (int it = 0; it < 16; ++it) {
        int idx = tid + it * 256;
        int r = idx >> 5, q = idx & 31;
        int n = n0 + r;
        float4 v = make_float4(0.f, 0.f, 0.f, 0.f);
        float4 a = make_float4(0.f, 0.f, 0.f, 0.f);
        if (n < NN) {
            v = __ldg((const float4*)(x + (size_t)n * 128) + q);
            float c = g_cnt[n];
            float inv = 1.0f / fmaxf(c, 1.0f);
            float4 ag = *((const float4*)(g_agg + (size_t)n * 128) + q);
            a = make_float4(ag.x * inv, ag.y * inv, ag.z * inv, ag.w * inv);
        }
        uint4 ux; ux.x = tf32c(v.x); ux.y = tf32c(v.y); ux.z = tf32c(v.z); ux.w = tf32c(v.w);
        uint4 ua; ua.x = tf32c(a.x); ua.y = tf32c(a.y); ua.z = tf32c(a.z); ua.w = tf32c(a.w);
        *(uint4*)(sXu + r * 132 + q * 4) = ux;
        *(uint4*)(sAu + r * 132 + q * 4) = ua;
    }
    __syncthreads();

    const int mrow0 = (w & 3) * 32;
    float acc[2][4][4];
#pragma unroll
    for (int mt = 0; mt < 2; ++mt)
#pragma unroll
        for (int nt = 0; nt < 4; ++nt)
#pragma unroll
            for (int p = 0; p < 4; ++p) acc[mt][nt][p] = 0.f;
    const int nc0s1 = (w >> 2) * 32;
#pragma unroll
    for (int kt = 0; kt < 32; ++kt) {
        const u32* src = (kt < 16) ? sXu : sAu;
        const int kc = (kt & 15) * 8;
        u32 a[2][4];
#pragma unroll
        for (int mt = 0; mt < 2; ++mt) {
            int base = (mrow0 + mt * 16 + g) * 132 + kc + t;
            a[mt][0] = src[base];
            a[mt][1] = src[base + 8 * 132];
            a[mt][2] = src[base + 4];
            a[mt][3] = src[base + 8 * 132 + 4];
        }
#pragma unroll
        for (int nt = 0; nt < 4; ++nt) {
            int ntg = (w >> 2) * 4 + nt;
            uint2 b = __ldg((const uint2*)g_n1img + ((ntg * 32 + kt) * 32 + lane));
            mma8(acc[0][nt], a[0], b);
            mma8(acc[1][nt], a[1], b);
        }
    }
#pragma unroll
    for (int mt = 0; mt < 2; ++mt)
#pragma unroll
        for (int nt = 0; nt < 4; ++nt) {
            int mr = mrow0 + mt * 16 + g;
            int nc = nc0s1 + nt * 8 + 2 * t;
            float b0 = __ldg(nb1 + nc), b1v = __ldg(nb1 + nc + 1);
            uint2 h0, h1;
            h0.x = tf32c(fmaxf(acc[mt][nt][0] + b0, 0.f));
            h0.y = tf32c(fmaxf(acc[mt][nt][1] + b1v, 0.f));
            h1.x = tf32c(fmaxf(acc[mt][nt][2] + b0, 0.f));
            h1.y = tf32c(fmaxf(acc[mt][nt][3] + b1v, 0.f));
            *(uint2*)(sHu + mr * 68 + nc) = h0;
            *(uint2*)(sHu + (mr + 8) * 68 + nc) = h1;
        }
    __syncthreads();
    float acc2[2][8][4];
#pragma unroll
    for (int mt = 0; mt < 2; ++mt)
#pragma unroll
        for (int nt = 0; nt < 8; ++nt)
#pragma unroll
            for (int p = 0; p < 4; ++p) acc2[mt][nt][p] = 0.f;
    const int nc0s2 = (w >> 2) * 64;
#pragma unroll
    for (int kt = 0; kt < 8; ++kt) {
        u32 a[2][4];
        const int kc = kt * 8;
#pragma unroll
        for (int mt = 0; mt < 2; ++mt) {
            int base = (mrow0 + mt * 16 + g) * 68 + kc + t;
            a[mt][0] = sHu[base];
            a[mt][1] = sHu[base + 8 * 68];
            a[mt][2] = sHu[base + 4];
            a[mt][3] = sHu[base + 8 * 68 + 4];
        }
#pragma unroll
        for (int nt = 0; nt < 8; ++nt) {
            int ntg = (w >> 2) * 8 + nt;
            uint2 b = __ldg((const uint2*)g_n2img + ((ntg * 8 + kt) * 32 + lane));
            mma8(acc2[0][nt], a[0], b);
            mma8(acc2[1][nt], a[1], b);
        }
    }
#pragma unroll
    for (int mt = 0; mt < 2; ++mt)
#pragma unroll
        for (int nt = 0; nt < 8; ++nt) {
            int mr = mrow0 + mt * 16 + g;
            int nc = nc0s2 + nt * 8 + 2 * t;
            *(float2*)(sOut + mr * 132 + nc)       = make_float2(acc2[mt][nt][0], acc2[mt][nt][1]);
            *(float2*)(sOut + (mr + 8) * 132 + nc) = make_float2(acc2[mt][nt][2], acc2[mt][nt][3]);
        }
    __syncthreads();
    {
        const int oct = tid & 7, rs = tid >> 3;
#pragma unroll
        for (int ov = 0; ov < 4; ++ov) {
            int r = ov * 32 + rs;
            int n = n0 + r;
            int nld = min(n, NN - 1);
            float4 vals[4];
            float s = 0.f, s2 = 0.f;
#pragma unroll
            for (int q = 0; q < 4; ++q) {
                int f4 = q * 8 + oct;
                float4 v = *(const float4*)(sOut + r * 132 + f4 * 4);
                float4 x4 = __ldg((const float4*)(x + (size_t)nld * 128) + f4);
                float4 b4 = __ldg((const float4*)nb2 + f4);
                v.x += x4.x + b4.x; v.y += x4.y + b4.y;
                v.z += x4.z + b4.z; v.w += x4.w + b4.w;
                vals[q] = v;
                s += v.x + v.y + v.z + v.w;
                s2 = fmaf(v.x, v.x, s2); s2 = fmaf(v.y, v.y, s2);
                s2 = fmaf(v.z, v.z, s2); s2 = fmaf(v.w, v.w, s2);
            }
            s  += __shfl_xor_sync(0xffffffffu, s, 1);  s2 += __shfl_xor_sync(0xffffffffu, s2, 1);
            s  += __shfl_xor_sync(0xffffffffu, s, 2);  s2 += __shfl_xor_sync(0xffffffffu, s2, 2);
            s  += __shfl_xor_sync(0xffffffffu, s, 4);  s2 += __shfl_xor_sync(0xffffffffu, s2, 4);
            const float mu   = s * 0.0078125f;
            const float var  = fmaf(-mu, mu, s2 * 0.0078125f);
            const float rstd = rsqrtf(var + 1e-5f);
            if (n < NN) {
                float* outb = xout + (size_t)n * 128;
#pragma unroll
                for (int q = 0; q < 4; ++q) {
                    int f4 = q * 8 + oct;
                    int j = f4 * 4;
                    float4 o;
                    o.x = fmaf((vals[q].x - mu) * rstd, __ldg(nx_g + j),     __ldg(nx_b + j));
                    o.y = fmaf((vals[q].y - mu) * rstd, __ldg(nx_g + j + 1), __ldg(nx_b + j + 1));
                    o.z = fmaf((vals[q].z - mu) * rstd, __ldg(nx_g + j + 2), __ldg(nx_b + j + 2));
                    o.w = fmaf((vals[q].w - mu) * rstd, __ldg(nx_g + j + 3), __ldg(nx_b + j + 3));
                    *(float4*)(outb + j) = o;
                }
            }
        }
    }
}

// --------------------------------- launch ---------------------------------------
extern "C" void kernel_launch(void* const* d_in, const int* in_sizes, int n_in,
                              void* d_out, int out_size) {
    const float* x   = (const float*)d_in[0];
    const void*  ei  = d_in[1];
    const float* ea  = (const float*)d_in[2];
    const float* ew1 = (const float*)d_in[4];
    const float* eb1 = (const float*)d_in[5];
    const float* ew2 = (const float*)d_in[6];
    const float* eb2 = (const float*)d_in[7];
    const float* nw1 = (const float*)d_in[8];
    const float* nb1 = (const float*)d_in[9];
    const float* nw2 = (const float*)d_in[10];
    const float* nb2 = (const float*)d_in[11];
    const float* nxg = (const float*)d_in[12];
    const float* nxb = (const float*)d_in[13];
    const float* neg_ = (const float*)d_in[14];
    const float* neb_ = (const float*)d_in[15];
    float* xout = (float*)d_out;
    float* eout = xout + (size_t)NN * 128;

    const int SM_PRE  = 67584;
    const int SM_EDGE = 103424;
    const int SM_NODE = 169984;
    cudaFuncSetAttribute(k_pre,  cudaFuncAttributeMaxDynamicSharedMemorySize, SM_PRE);
    cudaFuncSetAttribute(k_edge, cudaFuncAttributeMaxDynamicSharedMemorySize, SM_EDGE);
    cudaFuncSetAttribute(k_node, cudaFuncAttributeMaxDynamicSharedMemorySize, SM_NODE);

    k_detect<<<1, 32>>>((const u32*)ei);
    k_zero<<<1024, 256>>>();
    k_prep_w<<<224, 256>>>(ew1, ew2, nw1, nw2);
    k_pre <<<(NN + 127) / 128, 256, SM_PRE>>>(x, eb1);
    k_edge<<<NE / 128, 256, SM_EDGE>>>(ea, ei, eb2, neg_, neb_, eout);
    k_node<<<(NN + 127) / 128, 256, SM_NODE>>>(x, nb1, nb2, nxg, nxb, xout);
}

// round 13
// speedup vs baseline: 2.6196x; 1.1069x over previous
#include <cuda_runtime.h>
#include <cstdint>
#include <cstddef>

#define NN 100000
#define NE 640000

typedef unsigned int u32;

__device__ float g_pre[(size_t)NN * 128];
__device__ float g_agg[(size_t)NN * 128];
__device__ float g_cnt[NN];
__device__ int   g_is64;
__device__ u32   g_b1img[8192];    // edge stage1 B (We), tf32 lane-packed, Kt=16, Nt=8
__device__ u32   g_b2img[8192];    // edge stage2 B (ew2), Kt=8,  Nt=16
__device__ u32   g_pwimg[16384];   // pre B ([Wa|Wb]),     Kt=16, Nt=16
__device__ u32   g_n1img[16384];   // node stage1 B (nw1), Kt=32, Nt=8
__device__ u32   g_n2img[8192];    // node stage2 B (nw2), Kt=8,  Nt=16

__device__ __forceinline__ u32 tf32c(float f) {
    u32 r; asm("cvt.rna.tf32.f32 %0, %1;" : "=r"(r) : "f"(f)); return r;
}
__device__ __forceinline__ void mma8(float* c, const u32* a, uint2 b) {
    asm volatile(
        "mma.sync.aligned.m16n8k8.row.col.f32.tf32.tf32.f32 "
        "{%0,%1,%2,%3}, {%4,%5,%6,%7}, {%8,%9}, {%0,%1,%2,%3};"
        : "+f"(c[0]), "+f"(c[1]), "+f"(c[2]), "+f"(c[3])
        : "r"(a[0]), "r"(a[1]), "r"(a[2]), "r"(a[3]), "r"(b.x), "r"(b.y));
}

// -------- pack weight fragment images + detect edge_index dtype (one-time) ------
__global__ void k_prep_w(const float* __restrict__ ew1, const float* __restrict__ ew2,
                         const float* __restrict__ nw1, const float* __restrict__ nw2,
                         const u32* __restrict__ eiw) {
    if (blockIdx.x == 0 && threadIdx.x < 32) {   // detect int64 vs int32 indices
        u32 any = 0;
        for (int i = threadIdx.x; i < 1024; i += 32) any |= eiw[2 * i + 1];
#pragma unroll
        for (int o = 16; o > 0; o >>= 1) any |= __shfl_xor_sync(0xffffffffu, any, o);
        if (threadIdx.x == 0) g_is64 = (any == 0) ? 1 : 0;
    }
    int i = blockIdx.x * 256 + threadIdx.x;   // 0..57343
    if (i < 16384) {                           // g_pwimg: [Wa|Wb], K=128, N=128
        int part = i & 1, idx = i >> 1;
        int lane = idx & 31, kt = (idx >> 5) & 15, ntg = idx >> 9;
        int g = lane >> 2, t = lane & 3;
        int k = kt * 8 + t + part * 4, n = ntg * 8 + g;
        float v = (n < 64) ? __ldg(ew1 + (size_t)k * 64 + n)
                           : __ldg(ew1 + (size_t)(128 + k) * 64 + (n - 64));
        g_pwimg[i] = tf32c(v);
    } else if (i < 24576) {                    // g_b1img: We = ew1 rows 256..383
        int j = i - 16384, part = j & 1, idx = j >> 1;
        int lane = idx & 31, kt = (idx >> 5) & 15, ntg = idx >> 9;
        int g = lane >> 2, t = lane & 3;
        int k = kt * 8 + t + part * 4, n = ntg * 8 + g;
        g_b1img[j] = tf32c(__ldg(ew1 + (size_t)(256 + k) * 64 + n));
    } else if (i < 32768) {                    // g_b2img: ew2, K=64, N=128
        int j = i - 24576, part = j & 1, idx = j >> 1;
        int lane = idx & 31, kt = (idx >> 5) & 7, ntg = idx >> 8;
        int g = lane >> 2, t = lane & 3;
        int k = kt * 8 + t + part * 4, n = ntg * 8 + g;
        g_b2img[j] = tf32c(__ldg(ew2 + (size_t)k * 128 + n));
    } else if (i < 49152) {                    // g_n1img: nw1, K=256, N=64
        int j = i - 32768, part = j & 1, idx = j >> 1;
        int lane = idx & 31, kt = (idx >> 5) & 31, ntg = idx >> 10;
        int g = lane >> 2, t = lane & 3;
        int k = kt * 8 + t + part * 4, n = ntg * 8 + g;
        g_n1img[j] = tf32c(__ldg(nw1 + (size_t)k * 64 + n));
    } else {                                   // g_n2img: nw2, K=64, N=128
        int j = i - 49152, part = j & 1, idx = j >> 1;
        int lane = idx & 31, kt = (idx >> 5) & 7, ntg = idx >> 8;
        int g = lane >> 2, t = lane & 3;
        int k = kt * 8 + t + part * 4, n = ntg * 8 + g;
        g_n2img[j] = tf32c(__ldg(nw2 + (size_t)k * 128 + n));
    }
}

// ------------- kernel 1: pre = x @ [Wa|Wb] (+eb1) via mma.sync; zeroes agg/cnt ---
__global__ void __launch_bounds__(256, 2) k_pre(
    const float* __restrict__ x, const float* __restrict__ eb1) {
    extern __shared__ float smf[];
    u32* sXu = (u32*)smf;                     // tf32, stride 132
    const int tid = threadIdx.x;
    const int lane = tid & 31, w = tid >> 5;
    const int g = lane >> 2, t = lane & 3;
    const int n0 = blockIdx.x * 128;

    const float4 z4 = make_float4(0.f, 0.f, 0.f, 0.f);
#pragma unroll
    for (int it = 0; it < 16; ++it) {
        int idx = tid + it * 256;
        int r = idx >> 5, q = idx & 31;
        int n = n0 + r;
        float4 v = z4;
        if (n < NN) {
            v = __ldg((const float4*)(x + (size_t)n * 128) + q);
            *((float4*)(g_agg + (size_t)n * 128) + q) = z4;   // zero agg (fused k_zero)
        }
        uint4 u; u.x = tf32c(v.x); u.y = tf32c(v.y); u.z = tf32c(v.z); u.w = tf32c(v.w);
        *(uint4*)(sXu + r * 132 + q * 4) = u;
    }
    if (tid < 128 && n0 + tid < NN) g_cnt[n0 + tid] = 0.f;
    __syncthreads();

    const int mrow0 = (w & 3) * 32, wc = w >> 2;
    float acc[2][8][4];
#pragma unroll
    for (int mt = 0; mt < 2; ++mt)
#pragma unroll
        for (int nt = 0; nt < 8; ++nt)
#pragma unroll
            for (int p = 0; p < 4; ++p) acc[mt][nt][p] = 0.f;

#pragma unroll
    for (int kt = 0; kt < 16; ++kt) {
        u32 a[2][4];
        const int kc = kt * 8;
#pragma unroll
        for (int mt = 0; mt < 2; ++mt) {
            int base = (mrow0 + mt * 16 + g) * 132 + kc + t;
            a[mt][0] = sXu[base];
            a[mt][1] = sXu[base + 8 * 132];
            a[mt][2] = sXu[base + 4];
            a[mt][3] = sXu[base + 8 * 132 + 4];
        }
#pragma unroll
        for (int nt = 0; nt < 8; ++nt) {
            int ntg = wc * 8 + nt;
            uint2 b = __ldg((const uint2*)g_pwimg + ((ntg * 16 + kt) * 32 + lane));
            mma8(acc[0][nt], a[0], b);
            mma8(acc[1][nt], a[1], b);
        }
    }
#pragma unroll
    for (int mt = 0; mt < 2; ++mt)
#pragma unroll
        for (int nt = 0; nt < 8; ++nt) {
            int nc = wc * 64 + nt * 8 + 2 * t;
            float b0 = 0.f, b1v = 0.f;
            if (wc == 0) { b0 = __ldg(eb1 + nc); b1v = __ldg(eb1 + nc + 1); }
            int mr = mrow0 + mt * 16 + g;
            int n1 = n0 + mr, n2 = n0 + mr + 8;
            if (n1 < NN)
                *(float2*)(g_pre + (size_t)n1 * 128 + nc) =
                    make_float2(acc[mt][nt][0] + b0, acc[mt][nt][1] + b1v);
            if (n2 < NN)
                *(float2*)(g_pre + (size_t)n2 * 128 + nc) =
                    make_float2(acc[mt][nt][2] + b0, acc[mt][nt][3] + b1v);
        }
}

// ------------------- kernel 2: edges via mma.sync tf32 (R12, unchanged) ----------
__global__ void __launch_bounds__(256, 2) k_edge(
    const float* __restrict__ ea, const void* __restrict__ ei_raw,
    const float* __restrict__ eb2, const float* __restrict__ ne_g,
    const float* __restrict__ ne_b, float* __restrict__ eout) {
    extern __shared__ float smf[];
    char* smb = (char*)smf;
    int*   sCol = (int*)smb;
    const int E_B = 1024, PAB_B = 68608;
    u32*   sEu  = (u32*)(smb + E_B);
    float* sPAB = (float*)(smb + PAB_B);
    u32*   sHu  = (u32*)(smb + PAB_B);
    float* sOut = (float*)(smb + E_B);
    const int tid = threadIdx.x;
    const int lane = tid & 31, w = tid >> 5;
    const int g = lane >> 2, t = lane & 3;
    const int e0 = blockIdx.x * 128;
    const int is64 = g_is64;

    if (tid < 128) {
        int c;
        if (is64) c = (int)__ldg(((const long long*)ei_raw) + (size_t)NE + e0 + tid);
        else      c = __ldg(((const int*)ei_raw) + (size_t)NE + e0 + tid);
        sCol[tid] = min(max(c, 0), NN - 1);
    }
#pragma unroll
    for (int it = 0; it < 8; ++it) {
        int idx = tid + it * 256;
        int el = idx >> 4, q = idx & 15;
        int e = e0 + el; int rn, cn;
        if (is64) { const long long* p = (const long long*)ei_raw;
            rn = (int)__ldg(p + e); cn = (int)__ldg(p + (size_t)NE + e); }
        else { const int* p = (const int*)ei_raw;
            rn = __ldg(p + e); cn = __ldg(p + (size_t)NE + e); }
        rn = min(max(rn, 0), NN - 1); cn = min(max(cn, 0), NN - 1);
        float4 va = __ldg((const float4*)(g_pre + (size_t)rn * 128) + q);
        float4 vb = __ldg((const float4*)(g_pre + (size_t)cn * 128) + 16 + q);
        float* d = sPAB + el * 68 + q * 4;
        d[0] = va.x + vb.x; d[1] = va.y + vb.y;
        d[2] = va.z + vb.z; d[3] = va.w + vb.w;
    }
#pragma unroll
    for (int it = 0; it < 16; ++it) {
        int idx = tid + it * 256;
        int r = idx >> 5, q = idx & 31;
        float4 v = __ldg((const float4*)(ea + (size_t)(e0 + r) * 128) + q);
        uint4 u; u.x = tf32c(v.x); u.y = tf32c(v.y); u.z = tf32c(v.z); u.w = tf32c(v.w);
        *(uint4*)(sEu + r * 132 + q * 4) = u;
    }
    __syncthreads();

    const int mrow0 = (w & 3) * 32;
    float acc[2][4][4];
    const int nc0s1 = (w >> 2) * 32;
#pragma unroll
    for (int mt = 0; mt < 2; ++mt)
#pragma unroll
        for (int nt = 0; nt < 4; ++nt) {
            int mr = mrow0 + mt * 16 + g;
            int nc = nc0s1 + nt * 8 + 2 * t;
            float2 lo = *(const float2*)(sPAB + mr * 68 + nc);
            float2 hi = *(const float2*)(sPAB + (mr + 8) * 68 + nc);
            acc[mt][nt][0] = lo.x; acc[mt][nt][1] = lo.y;
            acc[mt][nt][2] = hi.x; acc[mt][nt][3] = hi.y;
        }
    __syncthreads();
#pragma unroll
    for (int kt = 0; kt < 16; ++kt) {
        u32 a[2][4];
        const int kc = kt * 8;
#pragma unroll
        for (int mt = 0; mt < 2; ++mt) {
            int base = (mrow0 + mt * 16 + g) * 132 + kc + t;
            a[mt][0] = sEu[base];
            a[mt][1] = sEu[base + 8 * 132];
            a[mt][2] = sEu[base + 4];
            a[mt][3] = sEu[base + 8 * 132 + 4];
        }
#pragma unroll
        for (int nt = 0; nt < 4; ++nt) {
            int ntg = (w >> 2) * 4 + nt;
            uint2 b = __ldg((const uint2*)g_b1img + ((ntg * 16 + kt) * 32 + lane));
            mma8(acc[0][nt], a[0], b);
            mma8(acc[1][nt], a[1], b);
        }
    }
#pragma unroll
    for (int mt = 0; mt < 2; ++mt)
#pragma unroll
        for (int nt = 0; nt < 4; ++nt) {
            int mr = mrow0 + mt * 16 + g;
            int nc = nc0s1 + nt * 8 + 2 * t;
            uint2 h0, h1;
            h0.x = tf32c(fmaxf(acc[mt][nt][0], 0.f));
            h0.y = tf32c(fmaxf(acc[mt][nt][1], 0.f));
            h1.x = tf32c(fmaxf(acc[mt][nt][2], 0.f));
            h1.y = tf32c(fmaxf(acc[mt][nt][3], 0.f));
            *(uint2*)(sHu + mr * 68 + nc) = h0;
            *(uint2*)(sHu + (mr + 8) * 68 + nc) = h1;
        }
    __syncthreads();
    float acc2[2][8][4];
#pragma unroll
    for (int mt = 0; mt < 2; ++mt)
#pragma unroll
        for (int nt = 0; nt < 8; ++nt)
#pragma unroll
            for (int p = 0; p < 4; ++p) acc2[mt][nt][p] = 0.f;
    const int nc0s2 = (w >> 2) * 64;
#pragma unroll
    for (int kt = 0; kt < 8; ++kt) {
        u32 a[2][4];
        const int kc = kt * 8;
#pragma unroll
        for (int mt = 0; mt < 2; ++mt) {
            int base = (mrow0 + mt * 16 + g) * 68 + kc + t;
            a[mt][0] = sHu[base];
            a[mt][1] = sHu[base + 8 * 68];
            a[mt][2] = sHu[base + 4];
            a[mt][3] = sHu[base + 8 * 68 + 4];
        }
#pragma unroll
        for (int nt = 0; nt < 8; ++nt) {
            int ntg = (w >> 2) * 8 + nt;
            uint2 b = __ldg((const uint2*)g_b2img + ((ntg * 8 + kt) * 32 + lane));
            mma8(acc2[0][nt], a[0], b);
            mma8(acc2[1][nt], a[1], b);
        }
    }
#pragma unroll
    for (int mt = 0; mt < 2; ++mt)
#pragma unroll
        for (int nt = 0; nt < 8; ++nt) {
            int mr = mrow0 + mt * 16 + g;
            int nc = nc0s2 + nt * 8 + 2 * t;
            *(float2*)(sOut + mr * 132 + nc)       = make_float2(acc2[mt][nt][0], acc2[mt][nt][1]);
            *(float2*)(sOut + (mr + 8) * 132 + nc) = make_float2(acc2[mt][nt][2], acc2[mt][nt][3]);
        }
    __syncthreads();
    {
        const int oct = tid & 7, rs = tid >> 3;
#pragma unroll
        for (int ov = 0; ov < 4; ++ov) {
            int r = ov * 32 + rs;
            float4 vals[4];
            float s = 0.f, s2 = 0.f;
#pragma unroll
            for (int q = 0; q < 4; ++q) {
                int f4 = q * 8 + oct;
                float4 v = *(const float4*)(sOut + r * 132 + f4 * 4);
                float4 e4 = __ldg((const float4*)(ea + (size_t)(e0 + r) * 128) + f4);
                float4 b4 = __ldg((const float4*)eb2 + f4);
                v.x += e4.x + b4.x; v.y += e4.y + b4.y;
                v.z += e4.z + b4.z; v.w += e4.w + b4.w;
                vals[q] = v;
                s += v.x + v.y + v.z + v.w;
                s2 = fmaf(v.x, v.x, s2); s2 = fmaf(v.y, v.y, s2);
                s2 = fmaf(v.z, v.z, s2); s2 = fmaf(v.w, v.w, s2);
            }
            s  += __shfl_xor_sync(0xffffffffu, s, 1);  s2 += __shfl_xor_sync(0xffffffffu, s2, 1);
            s  += __shfl_xor_sync(0xffffffffu, s, 2);  s2 += __shfl_xor_sync(0xffffffffu, s2, 2);
            s  += __shfl_xor_sync(0xffffffffu, s, 4);  s2 += __shfl_xor_sync(0xffffffffu, s2, 4);
            const float mu   = s * 0.0078125f;
            const float var  = fmaf(-mu, mu, s2 * 0.0078125f);
            const float rstd = rsqrtf(var + 1e-5f);
            const int cn = sCol[r];
            float4* aggb = (float4*)(g_agg + (size_t)cn * 128);
            float* outb = eout + (size_t)(e0 + r) * 128;
#pragma unroll
            for (int q = 0; q < 4; ++q) {
                int f4 = q * 8 + oct;
                atomicAdd(aggb + f4, vals[q]);
                int j = f4 * 4;
                float4 o;
                o.x = fmaf((vals[q].x - mu) * rstd, __ldg(ne_g + j),     __ldg(ne_b + j));
                o.y = fmaf((vals[q].y - mu) * rstd, __ldg(ne_g + j + 1), __ldg(ne_b + j + 1));
                o.z = fmaf((vals[q].z - mu) * rstd, __ldg(ne_g + j + 2), __ldg(ne_b + j + 2));
                o.w = fmaf((vals[q].w - mu) * rstd, __ldg(ne_g + j + 3), __ldg(ne_b + j + 3));
                *(float4*)(outb + j) = o;
            }
            if (oct == 0) atomicAdd(g_cnt + cn, 1.0f);
        }
    }
}

// ------------------- kernel 3: nodes, 64/block, 2 CTAs/SM ---------------------
// smem u32: sXu@0 (64*132=8448), sAu@8448, sHu@16896 (64*68=4352) -> 21248 u32 = 84992 B
__global__ void __launch_bounds__(256, 2) k_node(
    const float* __restrict__ x, const float* __restrict__ nb1,
    const float* __restrict__ nb2, const float* __restrict__ nx_g,
    const float* __restrict__ nx_b, float* __restrict__ xout) {
    extern __shared__ float smf[];
    u32* sXu = (u32*)smf;
    u32* sAu = sXu + 8448;
    u32* sHu = sXu + 16896;
    float* sOut = (float*)sXu;                // stride 132 fp32 (phase 2)
    const int tid = threadIdx.x;
    const int lane = tid & 31, w = tid >> 5;
    const int g = lane >> 2, t = lane & 3;
    const int n0 = blockIdx.x * 64;

#pragma unroll
    for (int it = 0; it < 8; ++it) {
        int idx = tid + it * 256;
        int r = idx >> 5, q = idx & 31;
        int n = n0 + r;
        float4 v = make_float4(0.f, 0.f, 0.f, 0.f);
        float4 a = make_float4(0.f, 0.f, 0.f, 0.f);
        if (n < NN) {
            v = __ldg((const float4*)(x + (size_t)n * 128) + q);
            float c = g_cnt[n];
            float inv = 1.0f / fmaxf(c, 1.0f);
            float4 ag = *((const float4*)(g_agg + (size_t)n * 128) + q);
            a = make_float4(ag.x * inv, ag.y * inv, ag.z * inv, ag.w * inv);
        }
        uint4 ux; ux.x = tf32c(v.x); ux.y = tf32c(v.y); ux.z = tf32c(v.z); ux.w = tf32c(v.w);
        uint4 ua; ua.x = tf32c(a.x); ua.y = tf32c(a.y); ua.z = tf32c(a.z); ua.w = tf32c(a.w);
        *(uint4*)(sXu + r * 132 + q * 4) = ux;
        *(uint4*)(sAu + r * 132 + q * 4) = ua;
    }
    __syncthreads();

    const int mrow0 = (w & 1) * 32, wc = w >> 1;      // 2 row panels x 4 col panels
    // stage 1: H[64x64] = [x|agg] @ nw1, K=256; warp tile 32x16
    float acc[2][2][4];
#pragma unroll
    for (int mt = 0; mt < 2; ++mt)
#pragma unroll
        for (int nt = 0; nt < 2; ++nt)
#pragma unroll
            for (int p = 0; p < 4; ++p) acc[mt][nt][p] = 0.f;
    const int nc0s1 = wc * 16;
#pragma unroll
    for (int kt = 0; kt < 32; ++kt) {
        const u32* src = (kt < 16) ? sXu : sAu;
        const int kc = (kt & 15) * 8;
        u32 a[2][4];
#pragma unroll
        for (int mt = 0; mt < 2; ++mt) {
            int base = (mrow0 + mt * 16 + g) * 132 + kc + t;
            a[mt][0] = src[base];
            a[mt][1] = src[base + 8 * 132];
            a[mt][2] = src[base + 4];
            a[mt][3] = src[base + 8 * 132 + 4];
        }
#pragma unroll
        for (int nt = 0; nt < 2; ++nt) {
            int ntg = wc * 2 + nt;
            uint2 b = __ldg((const uint2*)g_n1img + ((ntg * 32 + kt) * 32 + lane));
            mma8(acc[0][nt], a[0], b);
            mma8(acc[1][nt], a[1], b);
        }
    }
    // relu(acc + nb1) -> H tf32 (stride 68)
#pragma unroll
    for (int mt = 0; mt < 2; ++mt)
#pragma unroll
        for (int nt = 0; nt < 2; ++nt) {
            int mr = mrow0 + mt * 16 + g;
            int nc = nc0s1 + nt * 8 + 2 * t;
            float b0 = __ldg(nb1 + nc), b1v = __ldg(nb1 + nc + 1);
            uint2 h0, h1;
            h0.x = tf32c(fmaxf(acc[mt][nt][0] + b0, 0.f));
            h0.y = tf32c(fmaxf(acc[mt][nt][1] + b1v, 0.f));
            h1.x = tf32c(fmaxf(acc[mt][nt][2] + b0, 0.f));
            h1.y = tf32c(fmaxf(acc[mt][nt][3] + b1v, 0.f));
            *(uint2*)(sHu + mr * 68 + nc) = h0;
            *(uint2*)(sHu + (mr + 8) * 68 + nc) = h1;
        }
    __syncthreads();
    // stage 2: D2[64x128] = H @ nw2; warp tile 32x32
    float acc2[2][4][4];
#pragma unroll
    for (int mt = 0; mt < 2; ++mt)
#pragma unroll
        for (int nt = 0; nt < 4; ++nt)
#pragma unroll
            for (int p = 0; p < 4; ++p) acc2[mt][nt][p] = 0.f;
    const int nc0s2 = wc * 32;
#pragma unroll
    for (int kt = 0; kt < 8; ++kt) {
        u32 a[2][4];
        const int kc = kt * 8;
#pragma unroll
        for (int mt = 0; mt < 2; ++mt) {
            int base = (mrow0 + mt * 16 + g) * 68 + kc + t;
            a[mt][0] = sHu[base];
            a[mt][1] = sHu[base + 8 * 68];
            a[mt][2] = sHu[base + 4];
            a[mt][3] = sHu[base + 8 * 68 + 4];
        }
#pragma unroll
        for (int nt = 0; nt < 4; ++nt) {
            int ntg = wc * 4 + nt;
            uint2 b = __ldg((const uint2*)g_n2img + ((ntg * 8 + kt) * 32 + lane));
            mma8(acc2[0][nt], a[0], b);
            mma8(acc2[1][nt], a[1], b);
        }
    }
    // D2 -> sOut (reuses sXu region)
#pragma unroll
    for (int mt = 0; mt < 2; ++mt)
#pragma unroll
        for (int nt = 0; nt < 4; ++nt) {
            int mr = mrow0 + mt * 16 + g;
            int nc = nc0s2 + nt * 8 + 2 * t;
            *(float2*)(sOut + mr * 132 + nc)       = make_float2(acc2[mt][nt][0], acc2[mt][nt][1]);
            *(float2*)(sOut + (mr + 8) * 132 + nc) = make_float2(acc2[mt][nt][2], acc2[mt][nt][3]);
        }
    __syncthreads();
    // epilogue: x2 = D2 + x + nb2; LN -> xout (coalesced, 8 thr/row, 64 rows)
    {
        const int oct = tid & 7, rs = tid >> 3;
#pragma unroll
        for (int ov = 0; ov < 2; ++ov) {
            int r = ov * 32 + rs;
            int n = n0 + r;
            int nld = min(n, NN - 1);
            float4 vals[4];
            float s = 0.f, s2 = 0.f;
#pragma unroll
            for (int q = 0; q < 4; ++q) {
                int f4 = q * 8 + oct;
                float4 v = *(const float4*)(sOut + r * 132 + f4 * 4);
                float4 x4 = __ldg((const float4*)(x + (size_t)nld * 128) + f4);
                float4 b4 = __ldg((const float4*)nb2 + f4);
                v.x += x4.x + b4.x; v.y += x4.y + b4.y;
                v.z += x4.z + b4.z; v.w += x4.w + b4.w;
                vals[q] = v;
                s += v.x + v.y + v.z + v.w;
                s2 = fmaf(v.x, v.x, s2); s2 = fmaf(v.y, v.y, s2);
                s2 = fmaf(v.z, v.z, s2); s2 = fmaf(v.w, v.w, s2);
            }
            s  += __shfl_xor_sync(0xffffffffu, s, 1);  s2 += __shfl_xor_sync(0xffffffffu, s2, 1);
            s  += __shfl_xor_sync(0xffffffffu, s, 2);  s2 += __shfl_xor_sync(0xffffffffu, s2, 2);
            s  += __shfl_xor_sync(0xffffffffu, s, 4);  s2 += __shfl_xor_sync(0xffffffffu, s2, 4);
            const float mu   = s * 0.0078125f;
            const float var  = fmaf(-mu, mu, s2 * 0.0078125f);
            const float rstd = rsqrtf(var + 1e-5f);
            if (n < NN) {
                float* outb = xout + (size_t)n * 128;
#pragma unroll
                for (int q = 0; q < 4; ++q) {
                    int f4 = q * 8 + oct;
                    int j = f4 * 4;
                    float4 o;
                    o.x = fmaf((vals[q].x - mu) * rstd, __ldg(nx_g + j),     __ldg(nx_b + j));
                    o.y = fmaf((vals[q].y - mu) * rstd, __ldg(nx_g + j + 1), __ldg(nx_b + j + 1));
                    o.z = fmaf((vals[q].z - mu) * rstd, __ldg(nx_g + j + 2), __ldg(nx_b + j + 2));
                    o.w = fmaf((vals[q].w - mu) * rstd, __ldg(nx_g + j + 3), __ldg(nx_b + j + 3));
                    *(float4*)(outb + j) = o;
                }
            }
        }
    }
}

// --------------------------------- launch ---------------------------------------
extern "C" void kernel_launch(void* const* d_in, const int* in_sizes, int n_in,
                              void* d_out, int out_size) {
    const float* x   = (const float*)d_in[0];
    const void*  ei  = d_in[1];
    const float* ea  = (const float*)d_in[2];
    const float* ew1 = (const float*)d_in[4];
    const float* eb1 = (const float*)d_in[5];
    const float* ew2 = (const float*)d_in[6];
    const float* eb2 = (const float*)d_in[7];
    const float* nw1 = (const float*)d_in[8];
    const float* nb1 = (const float*)d_in[9];
    const float* nw2 = (const float*)d_in[10];
    const float* nb2 = (const float*)d_in[11];
    const float* nxg = (const float*)d_in[12];
    const float* nxb = (const float*)d_in[13];
    const float* neg_ = (const float*)d_in[14];
    const float* neb_ = (const float*)d_in[15];
    float* xout = (float*)d_out;
    float* eout = xout + (size_t)NN * 128;

    const int SM_PRE  = 67584;
    const int SM_EDGE = 103424;
    const int SM_NODE = 84992;
    cudaFuncSetAttribute(k_pre,  cudaFuncAttributeMaxDynamicSharedMemorySize, SM_PRE);
    cudaFuncSetAttribute(k_edge, cudaFuncAttributeMaxDynamicSharedMemorySize, SM_EDGE);
    cudaFuncSetAttribute(k_node, cudaFuncAttributeMaxDynamicSharedMemorySize, SM_NODE);

    k_prep_w<<<224, 256>>>(ew1, ew2, nw1, nw2, (const u32*)ei);
    k_pre <<<(NN + 127) / 128, 256, SM_PRE>>>(x, eb1);
    k_edge<<<NE / 128, 256, SM_EDGE>>>(ea, ei, eb2, neg_, neb_, eout);
    k_node<<<(NN + 63) / 64, 256, SM_NODE>>>(x, nb1, nb2, nxg, nxb, xout);
}